// round 2
// baseline (speedup 1.0000x reference)
#include <cuda_runtime.h>
#include <cuda_bf16.h>
#include <mma.h>

using namespace nvcuda;

// Problem constants
#define VV 32000
#define HH 1024
#define BB 32
#define SS 64
#define H3 3072
#define MM (SS*BB)   // 2048

// ---------------- scratch (device globals; no allocation allowed) ----------------
__device__ __nv_bfloat16 g_Xb[(size_t)MM*HH];        // relu(emb[tok]) bf16 hi  [S*B, H]
__device__ __nv_bfloat16 g_Xlo[(size_t)MM*HH];       // residual lo
__device__ __nv_bfloat16 g_Wihb[(size_t)H3*HH];      // W_ih bf16 hi
__device__ __nv_bfloat16 g_Wihlo[(size_t)H3*HH];     // W_ih bf16 lo
__device__ __nv_bfloat16 g_Woutb[(size_t)VV*HH];     // W_out bf16
__device__ __nv_bfloat16 g_HSb[(size_t)MM*HH];       // hs bf16
__device__ float g_GI[(size_t)MM*H3];                // x@W_ih^T + b_ih  [S*B, 3H]
__device__ float g_hs[(size_t)MM*HH];                // hidden states [S][B][H]
__device__ float g_ghp[(size_t)2*BB*H3];             // per-step k-split partials

// ---------------- fp32 -> bf16 convert (vectorized) ----------------
__global__ void f2b_kernel(const float* __restrict__ in, __nv_bfloat16* __restrict__ out, size_t n4)
{
    size_t i = (size_t)blockIdx.x * blockDim.x + threadIdx.x;
    if (i >= n4) return;
    float4 v = reinterpret_cast<const float4*>(in)[i];
    __nv_bfloat162 lo = __floats2bfloat162_rn(v.x, v.y);
    __nv_bfloat162 hi = __floats2bfloat162_rn(v.z, v.w);
    reinterpret_cast<__nv_bfloat162*>(out)[2*i]   = lo;
    reinterpret_cast<__nv_bfloat162*>(out)[2*i+1] = hi;
}

// ---------------- fp32 -> bf16 hi/lo split ----------------
__global__ void f2b_split_kernel(const float* __restrict__ in,
                                 __nv_bfloat16* __restrict__ hi,
                                 __nv_bfloat16* __restrict__ lo, size_t n4)
{
    size_t i = (size_t)blockIdx.x * blockDim.x + threadIdx.x;
    if (i >= n4) return;
    float4 v = reinterpret_cast<const float4*>(in)[i];
    float a[4] = {v.x, v.y, v.z, v.w};
    __nv_bfloat16 h[4], l[4];
    #pragma unroll
    for (int k=0;k<4;k++) {
        h[k] = __float2bfloat16(a[k]);
        l[k] = __float2bfloat16(a[k] - __bfloat162float(h[k]));
    }
    reinterpret_cast<__nv_bfloat162*>(hi)[2*i]   = __nv_bfloat162{h[0],h[1]};
    reinterpret_cast<__nv_bfloat162*>(hi)[2*i+1] = __nv_bfloat162{h[2],h[3]};
    reinterpret_cast<__nv_bfloat162*>(lo)[2*i]   = __nv_bfloat162{l[0],l[1]};
    reinterpret_cast<__nv_bfloat162*>(lo)[2*i+1] = __nv_bfloat162{l[2],l[3]};
}

// ---------------- embedding gather + relu -> bf16 hi/lo ----------------
__global__ void embed_kernel(const float* __restrict__ emb, const int* __restrict__ tgt,
                             const int* __restrict__ bos)
{
    int row = blockIdx.x;            // row = t*B + b
    int t = row >> 5, b = row & 31;  // B = 32
    int tok = (t == 0) ? bos[0] : tgt[b*SS + t - 1];
    const float* e = &emb[(size_t)tok * HH];
    for (int i = threadIdx.x; i < HH; i += blockDim.x) {
        float v = e[i];
        v = v > 0.f ? v : 0.f;
        __nv_bfloat16 h = __float2bfloat16(v);
        g_Xb [(size_t)row*HH + i] = h;
        g_Xlo[(size_t)row*HH + i] = __float2bfloat16(v - __bfloat162float(h));
    }
}

// ---------------- generic bf16 GEMM: C[M,N] = A[M,K] * B[N,K]^T (+bias) (+C) ----------------
// remap=1: GEMM row m (= s*B+b) is written to output row b*S+s (for [B,S,V] layout).
// accum=1: add existing C contents. bias may be null.
__global__ void gemm_bf16_kernel(const __nv_bfloat16* __restrict__ A,
                                 const __nv_bfloat16* __restrict__ Bm,
                                 float* __restrict__ C,
                                 const float* __restrict__ bias,
                                 int M, int N, int K, int remap, int accum)
{
    __shared__ __nv_bfloat16 SA[128][40];
    __shared__ __nv_bfloat16 SB[128][40];
    __shared__ float CS[8][256];

    int tid = threadIdx.x;
    int warp = tid >> 5, lane = tid & 31;
    int bm = blockIdx.y * 128, bn = blockIdx.x * 128;
    int wm = (warp >> 1) * 32;   // 0..96
    int wn = (warp & 1) * 64;    // 0 or 64

    wmma::fragment<wmma::accumulator,16,16,16,float> acc[2][4];
    #pragma unroll
    for (int i=0;i<2;i++)
        #pragma unroll
        for (int j=0;j<4;j++) wmma::fill_fragment(acc[i][j], 0.0f);

    int row = tid >> 1;
    int col = (tid & 1) * 16;

    for (int kc = 0; kc < K; kc += 32) {
        const uint4* pa = reinterpret_cast<const uint4*>(&A[(size_t)(bm+row)*K + kc + col]);
        uint4 va0 = pa[0], va1 = pa[1];
        *reinterpret_cast<uint4*>(&SA[row][col])   = va0;
        *reinterpret_cast<uint4*>(&SA[row][col+8]) = va1;
        const uint4* pb = reinterpret_cast<const uint4*>(&Bm[(size_t)(bn+row)*K + kc + col]);
        uint4 vb0 = pb[0], vb1 = pb[1];
        *reinterpret_cast<uint4*>(&SB[row][col])   = vb0;
        *reinterpret_cast<uint4*>(&SB[row][col+8]) = vb1;
        __syncthreads();
        #pragma unroll
        for (int ks = 0; ks < 2; ks++) {
            wmma::fragment<wmma::matrix_a,16,16,16,__nv_bfloat16,wmma::row_major> af[2];
            wmma::fragment<wmma::matrix_b,16,16,16,__nv_bfloat16,wmma::col_major> bf[4];
            #pragma unroll
            for (int i=0;i<2;i++) wmma::load_matrix_sync(af[i], &SA[wm+i*16][ks*16], 40);
            #pragma unroll
            for (int j=0;j<4;j++) wmma::load_matrix_sync(bf[j], &SB[wn+j*16][ks*16], 40);
            #pragma unroll
            for (int i=0;i<2;i++)
                #pragma unroll
                for (int j=0;j<4;j++)
                    wmma::mma_sync(acc[i][j], af[i], bf[j], acc[i][j]);
        }
        __syncthreads();
    }

    #pragma unroll
    for (int i=0;i<2;i++) {
        #pragma unroll
        for (int j=0;j<4;j++) {
            wmma::store_matrix_sync(&CS[warp][0], acc[i][j], 16, wmma::mem_row_major);
            __syncwarp();
            #pragma unroll
            for (int e=0;e<8;e++) {
                int idx = lane*8 + e;
                int r = idx >> 4, c = idx & 15;
                int gr = bm + wm + i*16 + r;
                int gc = bn + wn + j*16 + c;
                float v = CS[warp][idx];
                if (bias)  v += bias[gc];
                int orow = remap ? ((gr & 31) * SS + (gr >> 5)) : gr;
                if (accum) v += C[(size_t)orow * N + gc];
                C[(size_t)orow * N + gc] = v;
            }
            __syncwarp();
        }
    }
}

// ---------------- GRU step: gh partials (fp32, k-split x2) ----------------
// grid (96, 2), block 256. Writes g_ghp[(ksplit*32 + b)*3072 + j]
__global__ void gru_gh_kernel(const float* __restrict__ h0, const float* __restrict__ Whh, int t)
{
    __shared__ float sH[32][33];
    __shared__ float sW[32][33];
    const float* hprev = (t == 0) ? h0 : &g_hs[(size_t)(t-1)*BB*HH];
    int jt = blockIdx.x * 32;
    int k0 = blockIdx.y * 512;
    int tid = threadIdx.x;
    int kq = tid & 31;
    int rq = tid >> 5;   // 0..7
    int jl = tid & 31;
    int bq = tid >> 5;   // 0..7 -> b = bq*4 + i
    float acc0=0.f, acc1=0.f, acc2=0.f, acc3=0.f;

    for (int kc = 0; kc < 512; kc += 32) {
        #pragma unroll
        for (int i=0;i<4;i++) {
            sH[kq][rq + 8*i] = hprev[(rq + 8*i)*HH + k0 + kc + kq];
            sW[kq][rq + 8*i] = Whh[(size_t)(jt + rq + 8*i)*HH + k0 + kc + kq];
        }
        __syncthreads();
        #pragma unroll
        for (int k=0;k<32;k++) {
            float w = sW[k][jl];
            acc0 += sH[k][bq*4+0]*w;
            acc1 += sH[k][bq*4+1]*w;
            acc2 += sH[k][bq*4+2]*w;
            acc3 += sH[k][bq*4+3]*w;
        }
        __syncthreads();
    }
    size_t base = (size_t)(blockIdx.y*BB)*H3 + jt + jl;
    g_ghp[base + (size_t)(bq*4+0)*H3] = acc0;
    g_ghp[base + (size_t)(bq*4+1)*H3] = acc1;
    g_ghp[base + (size_t)(bq*4+2)*H3] = acc2;
    g_ghp[base + (size_t)(bq*4+3)*H3] = acc3;
}

// ---------------- GRU gate update (fused, fp32) ----------------
__global__ void gru_gate_kernel(const float* __restrict__ h0, const float* __restrict__ bhh, int t)
{
    int idx = blockIdx.x*blockDim.x + threadIdx.x;  // 0..32767
    int b = idx >> 10, j = idx & 1023;
    const float* hprev = (t == 0) ? h0 : &g_hs[(size_t)(t-1)*BB*HH];
    const float* gi = &g_GI[(size_t)(t*BB + b)*H3];
    size_t p0 = (size_t)b*H3 + j;
    size_t p1 = (size_t)(BB+b)*H3 + j;
    float ghr = g_ghp[p0]        + g_ghp[p1]        + bhh[j];
    float ghz = g_ghp[p0 + HH]   + g_ghp[p1 + HH]   + bhh[HH + j];
    float ghn = g_ghp[p0 + 2*HH] + g_ghp[p1 + 2*HH] + bhh[2*HH + j];
    float r = 1.f/(1.f + expf(-(gi[j] + ghr)));
    float z = 1.f/(1.f + expf(-(gi[HH + j] + ghz)));
    float n = tanhf(gi[2*HH + j] + r*ghn);
    float h = (1.f - z)*n + z*hprev[idx];
    g_hs[(size_t)t*BB*HH + idx] = h;
}

// ---------------- log_softmax in place over rows of d_out ----------------
__global__ void lsm_kernel(float* __restrict__ out)
{
    __shared__ float red[256];
    float* p = out + (size_t)blockIdx.x * VV;
    float m = -1e30f;
    for (int i = threadIdx.x; i < VV; i += 256) m = fmaxf(m, p[i]);
    red[threadIdx.x] = m; __syncthreads();
    for (int s=128; s>0; s>>=1) { if (threadIdx.x < s) red[threadIdx.x] = fmaxf(red[threadIdx.x], red[threadIdx.x+s]); __syncthreads(); }
    m = red[0]; __syncthreads();
    float sum = 0.f;
    for (int i = threadIdx.x; i < VV; i += 256) sum += expf(p[i] - m);
    red[threadIdx.x] = sum; __syncthreads();
    for (int s=128; s>0; s>>=1) { if (threadIdx.x < s) red[threadIdx.x] += red[threadIdx.x+s]; __syncthreads(); }
    float lse = m + logf(red[0]);
    for (int i = threadIdx.x; i < VV; i += 256) p[i] -= lse;
}

// ---------------- final hidden state tail copy ----------------
__global__ void ht_kernel(float* __restrict__ out)
{
    int i = blockIdx.x*blockDim.x + threadIdx.x;
    if (i < BB*HH) out[(size_t)BB*SS*VV + i] = g_hs[(size_t)(SS-1)*BB*HH + i];
}

// ---------------- launch ----------------
extern "C" void kernel_launch(void* const* d_in, const int* in_sizes, int n_in,
                              void* d_out, int out_size)
{
    const float* enc_hidden = (const float*)d_in[1];   // [1,B,H]
    const int*   bos        = (const int*)  d_in[2];
    const int*   tgt        = (const int*)  d_in[3];   // [B,S]
    const float* emb        = (const float*)d_in[4];   // [V,H]
    const float* W_ih       = (const float*)d_in[5];   // [3H,H]
    const float* W_hh       = (const float*)d_in[6];   // [3H,H]
    const float* b_ih       = (const float*)d_in[7];
    const float* b_hh       = (const float*)d_in[8];
    const float* W_out      = (const float*)d_in[9];   // [V,H]
    const float* b_out      = (const float*)d_in[10];
    float* out = (float*)d_out;

    __nv_bfloat16 *Xb, *Xlo, *Wihb, *Wihlo, *Woutb, *HSb;
    float *GI, *hs;
    cudaGetSymbolAddress((void**)&Xb,    g_Xb);
    cudaGetSymbolAddress((void**)&Xlo,   g_Xlo);
    cudaGetSymbolAddress((void**)&Wihb,  g_Wihb);
    cudaGetSymbolAddress((void**)&Wihlo, g_Wihlo);
    cudaGetSymbolAddress((void**)&Woutb, g_Woutb);
    cudaGetSymbolAddress((void**)&HSb,   g_HSb);
    cudaGetSymbolAddress((void**)&GI,    g_GI);
    cudaGetSymbolAddress((void**)&hs,    g_hs);

    // weight conversions
    {
        size_t n4 = (size_t)H3*HH/4;
        f2b_split_kernel<<<(unsigned)((n4+255)/256), 256>>>(W_ih, Wihb, Wihlo, n4);
    }
    {
        size_t n4 = (size_t)VV*HH/4;
        f2b_kernel<<<(unsigned)((n4+255)/256), 256>>>(W_out, Woutb, n4);
    }

    // embedding + relu (hi/lo split)
    embed_kernel<<<MM, 256>>>(emb, tgt, bos);

    // GI = X @ W_ih^T + b_ih   [2048 x 3072], compensated bf16 (3 GEMMs)
    gemm_bf16_kernel<<<dim3(H3/128, MM/128), 256>>>(Xb,  Wihb,  GI, b_ih,   MM, H3, HH, 0, 0);
    gemm_bf16_kernel<<<dim3(H3/128, MM/128), 256>>>(Xb,  Wihlo, GI, nullptr,MM, H3, HH, 0, 1);
    gemm_bf16_kernel<<<dim3(H3/128, MM/128), 256>>>(Xlo, Wihb,  GI, nullptr,MM, H3, HH, 0, 1);

    // sequential GRU
    for (int t = 0; t < SS; t++) {
        gru_gh_kernel<<<dim3(96, 2), 256>>>(enc_hidden, W_hh, t);
        gru_gate_kernel<<<128, 256>>>(enc_hidden, b_hh, t);
    }

    // hs -> bf16
    {
        size_t n4 = (size_t)MM*HH/4;
        f2b_kernel<<<(unsigned)((n4+255)/256), 256>>>(hs, HSb, n4);
    }

    // logits = hs @ W_out^T + b_out -> d_out (remapped to [B,S,V])
    gemm_bf16_kernel<<<dim3(VV/128, MM/128), 256>>>(HSb, Woutb, out, b_out, MM, VV, HH, 1, 0);

    // log_softmax in place
    lsm_kernel<<<MM, 256>>>(out);

    // hT tail
    ht_kernel<<<128, 256>>>(out);
}

// round 3
// speedup vs baseline: 1.3031x; 1.3031x over previous
#include <cuda_runtime.h>
#include <cuda_bf16.h>
#include <mma.h>
#include <cstdint>

using namespace nvcuda;

#define VV 32000
#define HH 1024
#define BB 32
#define SS 64
#define H3 3072
#define MM (SS*BB)   // 2048

// ---------------- scratch ----------------
__device__ __nv_bfloat16 g_Xb[(size_t)MM*HH];        // relu(emb) hi
__device__ __nv_bfloat16 g_Xlo[(size_t)MM*HH];       // relu(emb) lo
__device__ __nv_bfloat16 g_Wihb[(size_t)H3*HH];
__device__ __nv_bfloat16 g_Wihlo[(size_t)H3*HH];
__device__ __nv_bfloat16 g_Whhb[(size_t)H3*HH];
__device__ __nv_bfloat16 g_Whhlo[(size_t)H3*HH];
__device__ __nv_bfloat16 g_Woutb[(size_t)VV*HH];
__device__ __nv_bfloat16 g_HSb[(size_t)MM*HH];       // hs bf16 (for output GEMM)
__device__ float g_GI[(size_t)MM*H3];                // x@W_ih^T (no bias)
__device__ float g_hf[2][BB*HH];                     // h fp32 ping-pong
__device__ __nv_bfloat16 g_hhi[2][BB*HH];
__device__ __nv_bfloat16 g_hlo[2][BB*HH];

// ---------------- cp.async helpers ----------------
__device__ __forceinline__ uint32_t smem_u32(const void* p){
    return (uint32_t)__cvta_generic_to_shared(p);
}
__device__ __forceinline__ void cp16(void* dst, const void* src){
    asm volatile("cp.async.cg.shared.global [%0], [%1], 16;" :: "r"(smem_u32(dst)), "l"(src));
}
__device__ __forceinline__ void cp_commit(){ asm volatile("cp.async.commit_group;"); }
template<int N> __device__ __forceinline__ void cp_wait(){ asm volatile("cp.async.wait_group %0;" :: "n"(N)); }

// ---------------- fp32 -> bf16 ----------------
__global__ void f2b_kernel(const float* __restrict__ in, __nv_bfloat16* __restrict__ out, size_t n4)
{
    size_t i = (size_t)blockIdx.x * blockDim.x + threadIdx.x;
    if (i >= n4) return;
    float4 v = reinterpret_cast<const float4*>(in)[i];
    reinterpret_cast<__nv_bfloat162*>(out)[2*i]   = __floats2bfloat162_rn(v.x, v.y);
    reinterpret_cast<__nv_bfloat162*>(out)[2*i+1] = __floats2bfloat162_rn(v.z, v.w);
}

// ---------------- fp32 -> bf16 hi/lo split ----------------
__global__ void f2b_split_kernel(const float* __restrict__ in,
                                 __nv_bfloat16* __restrict__ hi,
                                 __nv_bfloat16* __restrict__ lo, size_t n4)
{
    size_t i = (size_t)blockIdx.x * blockDim.x + threadIdx.x;
    if (i >= n4) return;
    float4 v = reinterpret_cast<const float4*>(in)[i];
    float a[4] = {v.x, v.y, v.z, v.w};
    __nv_bfloat16 h[4], l[4];
    #pragma unroll
    for (int k=0;k<4;k++) {
        h[k] = __float2bfloat16(a[k]);
        l[k] = __float2bfloat16(a[k] - __bfloat162float(h[k]));
    }
    reinterpret_cast<__nv_bfloat162*>(hi)[2*i]   = __nv_bfloat162{h[0],h[1]};
    reinterpret_cast<__nv_bfloat162*>(hi)[2*i+1] = __nv_bfloat162{h[2],h[3]};
    reinterpret_cast<__nv_bfloat162*>(lo)[2*i]   = __nv_bfloat162{l[0],l[1]};
    reinterpret_cast<__nv_bfloat162*>(lo)[2*i+1] = __nv_bfloat162{l[2],l[3]};
}

// ---------------- embedding gather + relu -> bf16 hi/lo ----------------
__global__ void embed_kernel(const float* __restrict__ emb, const int* __restrict__ tgt,
                             const int* __restrict__ bos)
{
    int row = blockIdx.x;            // row = t*B + b
    int t = row >> 5, b = row & 31;
    int tok = (t == 0) ? bos[0] : tgt[b*SS + t - 1];
    const float* e = &emb[(size_t)tok * HH];
    for (int i = threadIdx.x; i < HH; i += blockDim.x) {
        float v = e[i];
        v = v > 0.f ? v : 0.f;
        __nv_bfloat16 h = __float2bfloat16(v);
        g_Xb [(size_t)row*HH + i] = h;
        g_Xlo[(size_t)row*HH + i] = __float2bfloat16(v - __bfloat162float(h));
    }
}

// ---------------- init h0 ----------------
__global__ void init_h_kernel(const float* __restrict__ enc)
{
    int i = blockIdx.x*256 + threadIdx.x;  // 32768
    float v = enc[i];
    g_hf[0][i] = v;
    __nv_bfloat16 h = __float2bfloat16(v);
    g_hhi[0][i] = h;
    g_hlo[0][i] = __float2bfloat16(v - __bfloat162float(h));
}

// ================= fused compensated GI GEMM =================
// C[M,N] = (Ah+Al)[M,K] * (Bh+Bl)[N,K]^T  (3-term), pipelined, KC=32
// dynamic smem: 4 stage-pairs of [128][40] bf16 -> 2 stages * 40960 = 81920
__global__ void __launch_bounds__(256) gemm_gi_kernel(
    const __nv_bfloat16* __restrict__ Ah, const __nv_bfloat16* __restrict__ Al,
    const __nv_bfloat16* __restrict__ Bh, const __nv_bfloat16* __restrict__ Bl,
    float* __restrict__ C, int N, int K)
{
    extern __shared__ char dsm[];
    // stage layout: [SAh, SAl, SBh, SBl] each 128*40 bf16 = 10240B
    int tid = threadIdx.x, warp = tid >> 5;
    int bm = blockIdx.y * 128, bn = blockIdx.x * 128;
    int wm = (warp >> 1) * 32, wn = (warp & 1) * 64;

    wmma::fragment<wmma::accumulator,16,16,16,float> acc[2][4];
    #pragma unroll
    for (int i=0;i<2;i++)
        #pragma unroll
        for (int j=0;j<4;j++) wmma::fill_fragment(acc[i][j], 0.0f);

    auto stage_ptr = [&](int s, int mat)->__nv_bfloat16* {
        return (__nv_bfloat16*)(dsm + (size_t)s*40960 + (size_t)mat*10240);
    };
    const __nv_bfloat16* srcs[4] = {Ah, Al, Bh, Bl};

    auto prefetch = [&](int s, int kc){
        #pragma unroll
        for (int i=0;i<8;i++){
            int cid = tid + i*256;          // 0..2047
            int mat = cid >> 9;             // 0..3
            int k2  = cid & 511;            // 0..511
            int r = k2 >> 2, c = (k2 & 3) * 8;
            int grow = (mat < 2 ? bm : bn) + r;
            cp16(stage_ptr(s,mat) + r*40 + c,
                 srcs[mat] + (size_t)grow*K + kc + c);
        }
        cp_commit();
    };

    const int NIT = K / 32;
    prefetch(0, 0);
    for (int it = 0; it < NIT; ++it){
        int s = it & 1;
        if (it + 1 < NIT){ prefetch(s^1, (it+1)*32); cp_wait<1>(); }
        else cp_wait<0>();
        __syncthreads();
        __nv_bfloat16* SAh = stage_ptr(s,0);
        __nv_bfloat16* SAl = stage_ptr(s,1);
        __nv_bfloat16* SBh = stage_ptr(s,2);
        __nv_bfloat16* SBl = stage_ptr(s,3);
        #pragma unroll
        for (int ks = 0; ks < 2; ks++){
            wmma::fragment<wmma::matrix_a,16,16,16,__nv_bfloat16,wmma::row_major> ah[2], al[2];
            wmma::fragment<wmma::matrix_b,16,16,16,__nv_bfloat16,wmma::col_major> bh[4], bl[4];
            #pragma unroll
            for (int i=0;i<2;i++){
                wmma::load_matrix_sync(ah[i], SAh + (wm+i*16)*40 + ks*16, 40);
                wmma::load_matrix_sync(al[i], SAl + (wm+i*16)*40 + ks*16, 40);
            }
            #pragma unroll
            for (int j=0;j<4;j++){
                wmma::load_matrix_sync(bh[j], SBh + (wn+j*16)*40 + ks*16, 40);
                wmma::load_matrix_sync(bl[j], SBl + (wn+j*16)*40 + ks*16, 40);
            }
            #pragma unroll
            for (int i=0;i<2;i++)
                #pragma unroll
                for (int j=0;j<4;j++){
                    wmma::mma_sync(acc[i][j], ah[i], bh[j], acc[i][j]);
                    wmma::mma_sync(acc[i][j], ah[i], bl[j], acc[i][j]);
                    wmma::mma_sync(acc[i][j], al[i], bh[j], acc[i][j]);
                }
        }
        __syncthreads();
    }
    // direct store (no bias; bias applied in gate kernel)
    #pragma unroll
    for (int i=0;i<2;i++)
        #pragma unroll
        for (int j=0;j<4;j++)
            wmma::store_matrix_sync(&C[(size_t)(bm+wm+i*16)*N + bn+wn+j*16],
                                    acc[i][j], N, wmma::mem_row_major);
}

// ================= pipelined output GEMM =================
// C[M,N] = A[M,K]*B[N,K]^T + bias, rows remapped (gr=t*B+b -> b*S+t), KC=64
// dynamic smem: SA/SB 2 stages of 128*72 bf16 (18432B each) + CS 8KB = 81920
__global__ void __launch_bounds__(256) gemm_out_kernel(
    const __nv_bfloat16* __restrict__ A, const __nv_bfloat16* __restrict__ B,
    float* __restrict__ C, const float* __restrict__ bias, int N, int K)
{
    extern __shared__ char dsm[];
    int tid = threadIdx.x, warp = tid >> 5, lane = tid & 31;
    int bm = blockIdx.y * 128, bn = blockIdx.x * 128;
    int wm = (warp >> 1) * 32, wn = (warp & 1) * 64;

    wmma::fragment<wmma::accumulator,16,16,16,float> acc[2][4];
    #pragma unroll
    for (int i=0;i<2;i++)
        #pragma unroll
        for (int j=0;j<4;j++) wmma::fill_fragment(acc[i][j], 0.0f);

    auto SA = [&](int s)->__nv_bfloat16* { return (__nv_bfloat16*)(dsm + (size_t)s*18432); };
    auto SB = [&](int s)->__nv_bfloat16* { return (__nv_bfloat16*)(dsm + 36864 + (size_t)s*18432); };
    float* CS = (float*)(dsm + 73728);

    auto prefetch = [&](int s, int kc){
        #pragma unroll
        for (int i=0;i<4;i++){
            int cid = tid*4 + i;           // 0..1023
            int r = cid >> 3, c = (cid & 7) * 8;
            cp16(SA(s) + r*72 + c, A + (size_t)(bm+r)*K + kc + c);
            cp16(SB(s) + r*72 + c, B + (size_t)(bn+r)*K + kc + c);
        }
        cp_commit();
    };

    const int NIT = K / 64;
    prefetch(0, 0);
    for (int it = 0; it < NIT; ++it){
        int s = it & 1;
        if (it + 1 < NIT){ prefetch(s^1, (it+1)*64); cp_wait<1>(); }
        else cp_wait<0>();
        __syncthreads();
        #pragma unroll
        for (int ks = 0; ks < 4; ks++){
            wmma::fragment<wmma::matrix_a,16,16,16,__nv_bfloat16,wmma::row_major> af[2];
            wmma::fragment<wmma::matrix_b,16,16,16,__nv_bfloat16,wmma::col_major> bf[4];
            #pragma unroll
            for (int i=0;i<2;i++) wmma::load_matrix_sync(af[i], SA(s) + (wm+i*16)*72 + ks*16, 72);
            #pragma unroll
            for (int j=0;j<4;j++) wmma::load_matrix_sync(bf[j], SB(s) + (wn+j*16)*72 + ks*16, 72);
            #pragma unroll
            for (int i=0;i<2;i++)
                #pragma unroll
                for (int j=0;j<4;j++)
                    wmma::mma_sync(acc[i][j], af[i], bf[j], acc[i][j]);
        }
        __syncthreads();
    }

    #pragma unroll
    for (int i=0;i<2;i++){
        #pragma unroll
        for (int j=0;j<4;j++){
            wmma::store_matrix_sync(CS + warp*256, acc[i][j], 16, wmma::mem_row_major);
            __syncwarp();
            #pragma unroll
            for (int e=0;e<8;e++){
                int idx = lane*8 + e;
                int r = idx >> 4, c = idx & 15;
                int gr = bm + wm + i*16 + r;
                int gc = bn + wn + j*16 + c;
                float v = CS[warp*256 + idx] + bias[gc];
                int orow = (gr & 31) * SS + (gr >> 5);    // [B,S] remap
                C[(size_t)orow * N + gc] = v;
            }
            __syncwarp();
        }
    }
}

// ================= fused GRU step (tensor-core gh + gate) =================
// grid 64 blocks, block 256. Block handles j-tile of 16 across all 3 gates.
// gh[32 x 48] = h[32,1024] @ Wsel[48,1024]^T, compensated bf16.
// dynamic smem: per stage: SHh[32][72], SHl[32][72], SWh[48][72], SWl[48][72]
//   = 160*72*2 = 23040B; 2 stages = 46080; CS 32*52*4 = 6656 -> total 52736
__global__ void __launch_bounds__(256) gru_step_kernel(
    const float* __restrict__ bih, const float* __restrict__ bhh, int t)
{
    extern __shared__ char dsm[];
    int tid = threadIdx.x, warp = tid >> 5;
    int j0 = blockIdx.x * 16;
    int cur = t & 1, nxt = cur ^ 1;

    const __nv_bfloat16* hhi = g_hhi[cur];
    const __nv_bfloat16* hlo = g_hlo[cur];

    auto SHh = [&](int s)->__nv_bfloat16* { return (__nv_bfloat16*)(dsm + (size_t)s*23040); };
    auto SHl = [&](int s)->__nv_bfloat16* { return (__nv_bfloat16*)(dsm + (size_t)s*23040 + 4608); };
    auto SWh = [&](int s)->__nv_bfloat16* { return (__nv_bfloat16*)(dsm + (size_t)s*23040 + 9216); };
    auto SWl = [&](int s)->__nv_bfloat16* { return (__nv_bfloat16*)(dsm + (size_t)s*23040 + 16128); };
    float* CS = (float*)(dsm + 46080);   // [32][52]

    wmma::fragment<wmma::accumulator,16,16,16,float> acc;
    wmma::fill_fragment(acc, 0.0f);
    int mi = warp & 1, ni = warp >> 1;   // warps 0..5 do mma

    auto prefetch = [&](int s, int kc){
        #pragma unroll
        for (int i=0;i<5;i++){
            int cid = tid + i*256;        // 0..1279
            if (cid < 512){               // SH hi/lo: 2 x 32 rows x 8 chunks
                int mat = cid >> 8, k2 = cid & 255;
                int r = k2 >> 3, c = (k2 & 7) * 8;
                const __nv_bfloat16* src = (mat ? hlo : hhi) + r*HH + kc + c;
                __nv_bfloat16* dst = (mat ? SHl(s) : SHh(s)) + r*72 + c;
                cp16(dst, src);
            } else {                      // SW hi/lo: 2 x 48 rows x 8 chunks
                int k2 = cid - 512;       // 0..767
                int mat = k2 >= 384; if (mat) k2 -= 384;
                int r = k2 >> 3, c = (k2 & 7) * 8;
                int wrow = (r >> 4) * HH + j0 + (r & 15);
                const __nv_bfloat16* src = (mat ? g_Whhlo : g_Whhb) + (size_t)wrow*HH + kc + c;
                __nv_bfloat16* dst = (mat ? SWl(s) : SWh(s)) + r*72 + c;
                cp16(dst, src);
            }
        }
        cp_commit();
    };

    const int NIT = HH / 64;  // 16
    prefetch(0, 0);
    for (int it = 0; it < NIT; ++it){
        int s = it & 1;
        if (it + 1 < NIT){ prefetch(s^1, (it+1)*64); cp_wait<1>(); }
        else cp_wait<0>();
        __syncthreads();
        if (warp < 6){
            #pragma unroll
            for (int ks = 0; ks < 4; ks++){
                wmma::fragment<wmma::matrix_a,16,16,16,__nv_bfloat16,wmma::row_major> ah, al;
                wmma::fragment<wmma::matrix_b,16,16,16,__nv_bfloat16,wmma::col_major> bh, bl;
                wmma::load_matrix_sync(ah, SHh(s) + (mi*16)*72 + ks*16, 72);
                wmma::load_matrix_sync(al, SHl(s) + (mi*16)*72 + ks*16, 72);
                wmma::load_matrix_sync(bh, SWh(s) + (ni*16)*72 + ks*16, 72);
                wmma::load_matrix_sync(bl, SWl(s) + (ni*16)*72 + ks*16, 72);
                wmma::mma_sync(acc, ah, bh, acc);
                wmma::mma_sync(acc, ah, bl, acc);
                wmma::mma_sync(acc, al, bh, acc);
            }
        }
        __syncthreads();
    }

    if (warp < 6)
        wmma::store_matrix_sync(CS + (mi*16)*52 + ni*16, acc, 52, wmma::mem_row_major);
    __syncthreads();

    // gate update: 32 b x 16 j = 512 elems, 2 per thread
    #pragma unroll
    for (int e = tid; e < 512; e += 256){
        int b = e >> 4, jl = e & 15;
        int j = j0 + jl;
        float ghr = CS[b*52 + jl];
        float ghz = CS[b*52 + 16 + jl];
        float ghn = CS[b*52 + 32 + jl];
        const float* gi = &g_GI[(size_t)(t*BB + b)*H3];
        float gir = gi[j]        + bih[j];
        float giz = gi[HH + j]   + bih[HH + j];
        float gin = gi[2*HH + j] + bih[2*HH + j];
        float r = 1.f/(1.f + expf(-(gir + ghr + bhh[j])));
        float z = 1.f/(1.f + expf(-(giz + ghz + bhh[HH + j])));
        float n = tanhf(gin + r*(ghn + bhh[2*HH + j]));
        float h = (1.f - z)*n + z*g_hf[cur][b*HH + j];
        g_hf[nxt][b*HH + j] = h;
        __nv_bfloat16 hb = __float2bfloat16(h);
        g_hhi[nxt][b*HH + j] = hb;
        g_hlo[nxt][b*HH + j] = __float2bfloat16(h - __bfloat162float(hb));
        g_HSb[(size_t)(t*BB + b)*HH + j] = hb;
    }
}

// ---------------- log_softmax in place (vectorized) ----------------
__global__ void lsm_kernel(float* __restrict__ out)
{
    __shared__ float red[256];
    float4* p = (float4*)(out + (size_t)blockIdx.x * VV);   // 8000 float4
    float m = -1e30f;
    for (int i = threadIdx.x; i < 8000; i += 256){
        float4 v = p[i];
        m = fmaxf(m, fmaxf(fmaxf(v.x, v.y), fmaxf(v.z, v.w)));
    }
    red[threadIdx.x] = m; __syncthreads();
    for (int s=128; s>0; s>>=1){ if (threadIdx.x < s) red[threadIdx.x] = fmaxf(red[threadIdx.x], red[threadIdx.x+s]); __syncthreads(); }
    m = red[0]; __syncthreads();
    float sum = 0.f;
    for (int i = threadIdx.x; i < 8000; i += 256){
        float4 v = p[i];
        sum += expf(v.x-m) + expf(v.y-m) + expf(v.z-m) + expf(v.w-m);
    }
    red[threadIdx.x] = sum; __syncthreads();
    for (int s=128; s>0; s>>=1){ if (threadIdx.x < s) red[threadIdx.x] += red[threadIdx.x+s]; __syncthreads(); }
    float lse = m + logf(red[0]);
    for (int i = threadIdx.x; i < 8000; i += 256){
        float4 v = p[i];
        v.x -= lse; v.y -= lse; v.z -= lse; v.w -= lse;
        p[i] = v;
    }
}

// ---------------- hT tail ----------------
__global__ void ht_kernel(float* __restrict__ out)
{
    int i = blockIdx.x*blockDim.x + threadIdx.x;
    if (i < BB*HH) out[(size_t)BB*SS*VV + i] = g_hf[0][i];
}

// ---------------- launch ----------------
extern "C" void kernel_launch(void* const* d_in, const int* in_sizes, int n_in,
                              void* d_out, int out_size)
{
    const float* enc_hidden = (const float*)d_in[1];
    const int*   bos        = (const int*)  d_in[2];
    const int*   tgt        = (const int*)  d_in[3];
    const float* emb        = (const float*)d_in[4];
    const float* W_ih       = (const float*)d_in[5];
    const float* W_hh       = (const float*)d_in[6];
    const float* b_ih       = (const float*)d_in[7];
    const float* b_hh       = (const float*)d_in[8];
    const float* W_out      = (const float*)d_in[9];
    const float* b_out      = (const float*)d_in[10];
    float* out = (float*)d_out;

    __nv_bfloat16 *Xb, *Xlo, *Wihb, *Wihlo, *Whhb, *Whhlo, *Woutb, *HSb;
    float *GI;
    cudaGetSymbolAddress((void**)&Xb,    g_Xb);
    cudaGetSymbolAddress((void**)&Xlo,   g_Xlo);
    cudaGetSymbolAddress((void**)&Wihb,  g_Wihb);
    cudaGetSymbolAddress((void**)&Wihlo, g_Wihlo);
    cudaGetSymbolAddress((void**)&Whhb,  g_Whhb);
    cudaGetSymbolAddress((void**)&Whhlo, g_Whhlo);
    cudaGetSymbolAddress((void**)&Woutb, g_Woutb);
    cudaGetSymbolAddress((void**)&HSb,   g_HSb);
    cudaGetSymbolAddress((void**)&GI,    g_GI);

    static int smem_set = 0;
    if (!smem_set){
        cudaFuncSetAttribute(gemm_gi_kernel,  cudaFuncAttributeMaxDynamicSharedMemorySize, 81920);
        cudaFuncSetAttribute(gemm_out_kernel, cudaFuncAttributeMaxDynamicSharedMemorySize, 81920);
        cudaFuncSetAttribute(gru_step_kernel, cudaFuncAttributeMaxDynamicSharedMemorySize, 52736);
        smem_set = 1;
    }

    // weight conversions
    {
        size_t n4 = (size_t)H3*HH/4;
        f2b_split_kernel<<<(unsigned)((n4+255)/256), 256>>>(W_ih, Wihb, Wihlo, n4);
        f2b_split_kernel<<<(unsigned)((n4+255)/256), 256>>>(W_hh, Whhb, Whhlo, n4);
    }
    {
        size_t n4 = (size_t)VV*HH/4;
        f2b_kernel<<<(unsigned)((n4+255)/256), 256>>>(W_out, Woutb, n4);
    }

    embed_kernel<<<MM, 256>>>(emb, tgt, bos);
    init_h_kernel<<<BB*HH/256, 256>>>(enc_hidden);

    // GI = X @ W_ih^T (compensated, single fused pass; bias added in gate)
    gemm_gi_kernel<<<dim3(H3/128, MM/128), 256, 81920>>>(Xb, Xlo, Wihb, Wihlo, GI, H3, HH);

    // sequential GRU: one kernel per step
    for (int t = 0; t < SS; t++)
        gru_step_kernel<<<64, 256, 52736>>>(b_ih, b_hh, t);

    // logits = hs @ W_out^T + b_out -> d_out (remapped to [B,S,V])
    gemm_out_kernel<<<dim3(VV/128, MM/128), 256, 81920>>>(HSb, Woutb, out, b_out, VV, HH);

    // log_softmax in place
    lsm_kernel<<<MM, 256>>>(out);

    // hT tail (final h lives in g_hf[0] after 64 steps)
    ht_kernel<<<128, 256>>>(out);
}

// round 4
// speedup vs baseline: 1.4442x; 1.1083x over previous
#include <cuda_runtime.h>
#include <cuda_bf16.h>
#include <mma.h>
#include <cstdint>

using namespace nvcuda;

#define VV 32000
#define HH 1024
#define BB 32
#define SS 64
#define H3 3072
#define MM (SS*BB)   // 2048

// ---------------- scratch ----------------
__device__ __nv_bfloat16 g_Xb[(size_t)MM*HH];
__device__ __nv_bfloat16 g_Xlo[(size_t)MM*HH];
__device__ __nv_bfloat16 g_Wihb[(size_t)H3*HH];
__device__ __nv_bfloat16 g_Wihlo[(size_t)H3*HH];
__device__ __nv_bfloat16 g_Whhb[(size_t)H3*HH];
__device__ __nv_bfloat16 g_Whhlo[(size_t)H3*HH];
__device__ __nv_bfloat16 g_Woutb[(size_t)VV*HH];
__device__ __nv_bfloat16 g_HSb[(size_t)MM*HH];
__device__ float g_GI[(size_t)MM*H3];
__device__ float g_hf[2][BB*HH];
__device__ __nv_bfloat16 g_hhi[2][BB*HH];
__device__ __nv_bfloat16 g_hlo[2][BB*HH];
__device__ int g_bar;                      // persistent-kernel barrier counter

// ---------------- cp.async helpers ----------------
__device__ __forceinline__ uint32_t smem_u32(const void* p){
    return (uint32_t)__cvta_generic_to_shared(p);
}
__device__ __forceinline__ void cp16(void* dst, const void* src){
    asm volatile("cp.async.cg.shared.global [%0], [%1], 16;" :: "r"(smem_u32(dst)), "l"(src));
}
__device__ __forceinline__ void cp_commit(){ asm volatile("cp.async.commit_group;"); }
template<int N> __device__ __forceinline__ void cp_wait(){ asm volatile("cp.async.wait_group %0;" :: "n"(N)); }

// ---------------- fp32 -> bf16 ----------------
__global__ void f2b_kernel(const float* __restrict__ in, __nv_bfloat16* __restrict__ out, size_t n4)
{
    size_t i = (size_t)blockIdx.x * blockDim.x + threadIdx.x;
    if (i >= n4) return;
    float4 v = reinterpret_cast<const float4*>(in)[i];
    reinterpret_cast<__nv_bfloat162*>(out)[2*i]   = __floats2bfloat162_rn(v.x, v.y);
    reinterpret_cast<__nv_bfloat162*>(out)[2*i+1] = __floats2bfloat162_rn(v.z, v.w);
}

// ---------------- fp32 -> bf16 hi/lo split ----------------
__global__ void f2b_split_kernel(const float* __restrict__ in,
                                 __nv_bfloat16* __restrict__ hi,
                                 __nv_bfloat16* __restrict__ lo, size_t n4)
{
    size_t i = (size_t)blockIdx.x * blockDim.x + threadIdx.x;
    if (i >= n4) return;
    float4 v = reinterpret_cast<const float4*>(in)[i];
    float a[4] = {v.x, v.y, v.z, v.w};
    __nv_bfloat16 h[4], l[4];
    #pragma unroll
    for (int k=0;k<4;k++) {
        h[k] = __float2bfloat16(a[k]);
        l[k] = __float2bfloat16(a[k] - __bfloat162float(h[k]));
    }
    reinterpret_cast<__nv_bfloat162*>(hi)[2*i]   = __nv_bfloat162{h[0],h[1]};
    reinterpret_cast<__nv_bfloat162*>(hi)[2*i+1] = __nv_bfloat162{h[2],h[3]};
    reinterpret_cast<__nv_bfloat162*>(lo)[2*i]   = __nv_bfloat162{l[0],l[1]};
    reinterpret_cast<__nv_bfloat162*>(lo)[2*i+1] = __nv_bfloat162{l[2],l[3]};
}

// ---------------- embedding gather + relu -> bf16 hi/lo ----------------
__global__ void embed_kernel(const float* __restrict__ emb, const int* __restrict__ tgt,
                             const int* __restrict__ bos)
{
    int row = blockIdx.x;            // row = t*B + b
    int t = row >> 5, b = row & 31;
    int tok = (t == 0) ? bos[0] : tgt[b*SS + t - 1];
    const float* e = &emb[(size_t)tok * HH];
    for (int i = threadIdx.x; i < HH; i += blockDim.x) {
        float v = e[i];
        v = v > 0.f ? v : 0.f;
        __nv_bfloat16 h = __float2bfloat16(v);
        g_Xb [(size_t)row*HH + i] = h;
        g_Xlo[(size_t)row*HH + i] = __float2bfloat16(v - __bfloat162float(h));
    }
}

// ---------------- init h0 + reset barrier ----------------
__global__ void init_h_kernel(const float* __restrict__ enc)
{
    int i = blockIdx.x*256 + threadIdx.x;  // 32768
    if (i == 0) g_bar = 0;
    float v = enc[i];
    g_hf[0][i] = v;
    __nv_bfloat16 h = __float2bfloat16(v);
    g_hhi[0][i] = h;
    g_hlo[0][i] = __float2bfloat16(v - __bfloat162float(h));
}

// ================= fused compensated GI GEMM =================
__global__ void __launch_bounds__(256) gemm_gi_kernel(
    const __nv_bfloat16* __restrict__ Ah, const __nv_bfloat16* __restrict__ Al,
    const __nv_bfloat16* __restrict__ Bh, const __nv_bfloat16* __restrict__ Bl,
    float* __restrict__ C, int N, int K)
{
    extern __shared__ char dsm[];
    int tid = threadIdx.x, warp = tid >> 5;
    int bm = blockIdx.y * 128, bn = blockIdx.x * 128;
    int wm = (warp >> 1) * 32, wn = (warp & 1) * 64;

    wmma::fragment<wmma::accumulator,16,16,16,float> acc[2][4];
    #pragma unroll
    for (int i=0;i<2;i++)
        #pragma unroll
        for (int j=0;j<4;j++) wmma::fill_fragment(acc[i][j], 0.0f);

    auto stage_ptr = [&](int s, int mat)->__nv_bfloat16* {
        return (__nv_bfloat16*)(dsm + (size_t)s*40960 + (size_t)mat*10240);
    };
    const __nv_bfloat16* srcs[4] = {Ah, Al, Bh, Bl};

    auto prefetch = [&](int s, int kc){
        #pragma unroll
        for (int i=0;i<8;i++){
            int cid = tid + i*256;
            int mat = cid >> 9;
            int k2  = cid & 511;
            int r = k2 >> 2, c = (k2 & 3) * 8;
            int grow = (mat < 2 ? bm : bn) + r;
            cp16(stage_ptr(s,mat) + r*40 + c, srcs[mat] + (size_t)grow*K + kc + c);
        }
        cp_commit();
    };

    const int NIT = K / 32;
    prefetch(0, 0);
    for (int it = 0; it < NIT; ++it){
        int s = it & 1;
        if (it + 1 < NIT){ prefetch(s^1, (it+1)*32); cp_wait<1>(); }
        else cp_wait<0>();
        __syncthreads();
        __nv_bfloat16* SAh = stage_ptr(s,0);
        __nv_bfloat16* SAl = stage_ptr(s,1);
        __nv_bfloat16* SBh = stage_ptr(s,2);
        __nv_bfloat16* SBl = stage_ptr(s,3);
        #pragma unroll
        for (int ks = 0; ks < 2; ks++){
            wmma::fragment<wmma::matrix_a,16,16,16,__nv_bfloat16,wmma::row_major> ah[2], al[2];
            wmma::fragment<wmma::matrix_b,16,16,16,__nv_bfloat16,wmma::col_major> bh[4], bl[4];
            #pragma unroll
            for (int i=0;i<2;i++){
                wmma::load_matrix_sync(ah[i], SAh + (wm+i*16)*40 + ks*16, 40);
                wmma::load_matrix_sync(al[i], SAl + (wm+i*16)*40 + ks*16, 40);
            }
            #pragma unroll
            for (int j=0;j<4;j++){
                wmma::load_matrix_sync(bh[j], SBh + (wn+j*16)*40 + ks*16, 40);
                wmma::load_matrix_sync(bl[j], SBl + (wn+j*16)*40 + ks*16, 40);
            }
            #pragma unroll
            for (int i=0;i<2;i++)
                #pragma unroll
                for (int j=0;j<4;j++){
                    wmma::mma_sync(acc[i][j], ah[i], bh[j], acc[i][j]);
                    wmma::mma_sync(acc[i][j], ah[i], bl[j], acc[i][j]);
                    wmma::mma_sync(acc[i][j], al[i], bh[j], acc[i][j]);
                }
        }
        __syncthreads();
    }
    #pragma unroll
    for (int i=0;i<2;i++)
        #pragma unroll
        for (int j=0;j<4;j++)
            wmma::store_matrix_sync(&C[(size_t)(bm+wm+i*16)*N + bn+wn+j*16],
                                    acc[i][j], N, wmma::mem_row_major);
}

// ================= output GEMM: 128x256 tile, 512 thr, 3-stage =================
// stage: SA 128x72 bf16 (18432B) + SB 256x72 bf16 (36864B) = 55296B; 3 stages = 165888
__global__ void __launch_bounds__(512) gemm_out_kernel(
    const __nv_bfloat16* __restrict__ A, const __nv_bfloat16* __restrict__ B,
    float* __restrict__ C, const float* __restrict__ bias, int N, int K)
{
    extern __shared__ char dsm[];
    int tid = threadIdx.x, warp = tid >> 5, lane = tid & 31;
    int bm = blockIdx.y * 128, bn = blockIdx.x * 256;
    int wm = (warp >> 2) * 32;        // 0..96
    int wn = (warp & 3) * 64;         // 0..192

    wmma::fragment<wmma::accumulator,16,16,16,float> acc[2][4];
    #pragma unroll
    for (int i=0;i<2;i++)
        #pragma unroll
        for (int j=0;j<4;j++) wmma::fill_fragment(acc[i][j], 0.0f);

    auto SA = [&](int s)->__nv_bfloat16* { return (__nv_bfloat16*)(dsm + (size_t)s*55296); };
    auto SB = [&](int s)->__nv_bfloat16* { return (__nv_bfloat16*)(dsm + (size_t)s*55296 + 18432); };

    auto prefetch = [&](int s, int kc){
        #pragma unroll
        for (int i=0;i<6;i++){
            int cid = tid + i*512;        // 0..3071
            if (cid < 1024){              // SA: 128 rows x 8 chunks
                int r = cid >> 3, c = (cid & 7) * 8;
                cp16(SA(s) + r*72 + c, A + (size_t)(bm+r)*K + kc + c);
            } else {                      // SB: 256 rows x 8 chunks
                int k2 = cid - 1024;
                int r = k2 >> 3, c = (k2 & 7) * 8;
                cp16(SB(s) + r*72 + c, B + (size_t)(bn+r)*K + kc + c);
            }
        }
        cp_commit();
    };

    const int NIT = K / 64;   // 16
    prefetch(0, 0);
    prefetch(1, 64);
    for (int it = 0; it < NIT; ++it){
        int s = it % 3;
        if (it + 2 < NIT){ prefetch((it+2)%3, (it+2)*64); cp_wait<2>(); }
        else if (it + 1 < NIT) cp_wait<1>();
        else cp_wait<0>();
        __syncthreads();
        #pragma unroll
        for (int ks = 0; ks < 4; ks++){
            wmma::fragment<wmma::matrix_a,16,16,16,__nv_bfloat16,wmma::row_major> af[2];
            wmma::fragment<wmma::matrix_b,16,16,16,__nv_bfloat16,wmma::col_major> bf[4];
            #pragma unroll
            for (int i=0;i<2;i++) wmma::load_matrix_sync(af[i], SA(s) + (wm+i*16)*72 + ks*16, 72);
            #pragma unroll
            for (int j=0;j<4;j++) wmma::load_matrix_sync(bf[j], SB(s) + (wn+j*16)*72 + ks*16, 72);
            #pragma unroll
            for (int i=0;i<2;i++)
                #pragma unroll
                for (int j=0;j<4;j++)
                    wmma::mma_sync(acc[i][j], af[i], bf[j], acc[i][j]);
        }
        __syncthreads();
    }

    float* CS = (float*)dsm;   // reuse stage memory (16 warps x 256 floats)
    #pragma unroll
    for (int i=0;i<2;i++){
        #pragma unroll
        for (int j=0;j<4;j++){
            wmma::store_matrix_sync(CS + warp*256, acc[i][j], 16, wmma::mem_row_major);
            __syncwarp();
            #pragma unroll
            for (int e=0;e<8;e++){
                int idx = lane*8 + e;
                int r = idx >> 4, c = idx & 15;
                int gr = bm + wm + i*16 + r;
                int gc = bn + wn + j*16 + c;
                float v = CS[warp*256 + idx] + bias[gc];
                int orow = (gr & 31) * SS + (gr >> 5);
                C[(size_t)orow * N + gc] = v;
            }
            __syncwarp();
        }
    }
}

// ================= persistent GRU kernel (all 64 steps, 64 blocks) =================
__global__ void __launch_bounds__(256) gru_persist_kernel(
    const float* __restrict__ bih, const float* __restrict__ bhh)
{
    extern __shared__ char dsm[];
    int tid = threadIdx.x, warp = tid >> 5;
    int j0 = blockIdx.x * 16;

    auto SHh = [&](int s)->__nv_bfloat16* { return (__nv_bfloat16*)(dsm + (size_t)s*23040); };
    auto SHl = [&](int s)->__nv_bfloat16* { return (__nv_bfloat16*)(dsm + (size_t)s*23040 + 4608); };
    auto SWh = [&](int s)->__nv_bfloat16* { return (__nv_bfloat16*)(dsm + (size_t)s*23040 + 9216); };
    auto SWl = [&](int s)->__nv_bfloat16* { return (__nv_bfloat16*)(dsm + (size_t)s*23040 + 16128); };
    float* CS = (float*)(dsm + 46080);   // [32][52]

    int mi = warp & 1, ni = warp >> 1;

    for (int t = 0; t < SS; ++t){
        int cur = t & 1, nxt = cur ^ 1;
        const __nv_bfloat16* hhi = g_hhi[cur];
        const __nv_bfloat16* hlo = g_hlo[cur];

        wmma::fragment<wmma::accumulator,16,16,16,float> acc;
        wmma::fill_fragment(acc, 0.0f);

        auto prefetch = [&](int s, int kc){
            #pragma unroll
            for (int i=0;i<5;i++){
                int cid = tid + i*256;        // 0..1279
                if (cid < 512){
                    int mat = cid >> 8, k2 = cid & 255;
                    int r = k2 >> 3, c = (k2 & 7) * 8;
                    const __nv_bfloat16* src = (mat ? hlo : hhi) + r*HH + kc + c;
                    __nv_bfloat16* dst = (mat ? SHl(s) : SHh(s)) + r*72 + c;
                    cp16(dst, src);
                } else {
                    int k2 = cid - 512;
                    int mat = k2 >= 384; if (mat) k2 -= 384;
                    int r = k2 >> 3, c = (k2 & 7) * 8;
                    int wrow = (r >> 4) * HH + j0 + (r & 15);
                    const __nv_bfloat16* src = (mat ? g_Whhlo : g_Whhb) + (size_t)wrow*HH + kc + c;
                    __nv_bfloat16* dst = (mat ? SWl(s) : SWh(s)) + r*72 + c;
                    cp16(dst, src);
                }
            }
            cp_commit();
        };

        const int NIT = HH / 64;  // 16
        prefetch(0, 0);
        for (int it = 0; it < NIT; ++it){
            int s = it & 1;
            if (it + 1 < NIT){ prefetch(s^1, (it+1)*64); cp_wait<1>(); }
            else cp_wait<0>();
            __syncthreads();
            if (warp < 6){
                #pragma unroll
                for (int ks = 0; ks < 4; ks++){
                    wmma::fragment<wmma::matrix_a,16,16,16,__nv_bfloat16,wmma::row_major> ah, al;
                    wmma::fragment<wmma::matrix_b,16,16,16,__nv_bfloat16,wmma::col_major> bh, bl;
                    wmma::load_matrix_sync(ah, SHh(s) + (mi*16)*72 + ks*16, 72);
                    wmma::load_matrix_sync(al, SHl(s) + (mi*16)*72 + ks*16, 72);
                    wmma::load_matrix_sync(bh, SWh(s) + (ni*16)*72 + ks*16, 72);
                    wmma::load_matrix_sync(bl, SWl(s) + (ni*16)*72 + ks*16, 72);
                    wmma::mma_sync(acc, ah, bh, acc);
                    wmma::mma_sync(acc, ah, bl, acc);
                    wmma::mma_sync(acc, al, bh, acc);
                }
            }
            __syncthreads();
        }

        if (warp < 6)
            wmma::store_matrix_sync(CS + (mi*16)*52 + ni*16, acc, 52, wmma::mem_row_major);
        __syncthreads();

        // gate update: 512 elems, 2 per thread
        #pragma unroll
        for (int e = tid; e < 512; e += 256){
            int b = e >> 4, jl = e & 15;
            int j = j0 + jl;
            float ghr = CS[b*52 + jl];
            float ghz = CS[b*52 + 16 + jl];
            float ghn = CS[b*52 + 32 + jl];
            const float* gi = &g_GI[(size_t)(t*BB + b)*H3];
            float gir = gi[j]        + bih[j];
            float giz = gi[HH + j]   + bih[HH + j];
            float gin = gi[2*HH + j] + bih[2*HH + j];
            float r = 1.f/(1.f + expf(-(gir + ghr + bhh[j])));
            float z = 1.f/(1.f + expf(-(giz + ghz + bhh[HH + j])));
            float n = tanhf(gin + r*(ghn + bhh[2*HH + j]));
            float h = (1.f - z)*n + z*g_hf[cur][b*HH + j];
            g_hf[nxt][b*HH + j] = h;
            __nv_bfloat16 hb = __float2bfloat16(h);
            g_hhi[nxt][b*HH + j] = hb;
            g_hlo[nxt][b*HH + j] = __float2bfloat16(h - __bfloat162float(hb));
            g_HSb[(size_t)(t*BB + b)*HH + j] = hb;
        }

        // grid-wide barrier (all 64 blocks co-resident)
        __threadfence();
        __syncthreads();
        if (tid == 0){
            atomicAdd(&g_bar, 1);
            int target = 64 * (t + 1);
            while (*(volatile int*)&g_bar < target) { }
        }
        __syncthreads();
    }
}

// ---------------- log_softmax in place (online max+sum, 2 passes) ----------------
__global__ void lsm_kernel(float* __restrict__ out)
{
    __shared__ float rm[256], rs[256];
    float4* p = (float4*)(out + (size_t)blockIdx.x * VV);   // 8000 float4
    float m = -1e30f, s = 0.f;
    for (int i = threadIdx.x; i < 8000; i += 256){
        float4 v = p[i];
        float a[4] = {v.x, v.y, v.z, v.w};
        #pragma unroll
        for (int k=0;k<4;k++){
            float x = a[k];
            if (x > m){ s = s * expf(m - x) + 1.f; m = x; }
            else s += expf(x - m);
        }
    }
    rm[threadIdx.x] = m; rs[threadIdx.x] = s; __syncthreads();
    for (int st=128; st>0; st>>=1){
        if (threadIdx.x < st){
            float m2 = rm[threadIdx.x+st], s2 = rs[threadIdx.x+st];
            float m1 = rm[threadIdx.x],    s1 = rs[threadIdx.x];
            float M = fmaxf(m1, m2);
            rm[threadIdx.x] = M;
            rs[threadIdx.x] = s1 * expf(m1 - M) + s2 * expf(m2 - M);
        }
        __syncthreads();
    }
    float lse = rm[0] + logf(rs[0]);
    for (int i = threadIdx.x; i < 8000; i += 256){
        float4 v = p[i];
        v.x -= lse; v.y -= lse; v.z -= lse; v.w -= lse;
        p[i] = v;
    }
}

// ---------------- hT tail ----------------
__global__ void ht_kernel(float* __restrict__ out)
{
    int i = blockIdx.x*blockDim.x + threadIdx.x;
    if (i < BB*HH) out[(size_t)BB*SS*VV + i] = g_hf[0][i];
}

// ---------------- launch ----------------
extern "C" void kernel_launch(void* const* d_in, const int* in_sizes, int n_in,
                              void* d_out, int out_size)
{
    const float* enc_hidden = (const float*)d_in[1];
    const int*   bos        = (const int*)  d_in[2];
    const int*   tgt        = (const int*)  d_in[3];
    const float* emb        = (const float*)d_in[4];
    const float* W_ih       = (const float*)d_in[5];
    const float* W_hh       = (const float*)d_in[6];
    const float* b_ih       = (const float*)d_in[7];
    const float* b_hh       = (const float*)d_in[8];
    const float* W_out      = (const float*)d_in[9];
    const float* b_out      = (const float*)d_in[10];
    float* out = (float*)d_out;

    __nv_bfloat16 *Xb, *Xlo, *Wihb, *Wihlo, *Whhb, *Whhlo, *Woutb, *HSb;
    float *GI;
    cudaGetSymbolAddress((void**)&Xb,    g_Xb);
    cudaGetSymbolAddress((void**)&Xlo,   g_Xlo);
    cudaGetSymbolAddress((void**)&Wihb,  g_Wihb);
    cudaGetSymbolAddress((void**)&Wihlo, g_Wihlo);
    cudaGetSymbolAddress((void**)&Whhb,  g_Whhb);
    cudaGetSymbolAddress((void**)&Whhlo, g_Whhlo);
    cudaGetSymbolAddress((void**)&Woutb, g_Woutb);
    cudaGetSymbolAddress((void**)&HSb,   g_HSb);
    cudaGetSymbolAddress((void**)&GI,    g_GI);

    static int smem_set = 0;
    if (!smem_set){
        cudaFuncSetAttribute(gemm_gi_kernel,     cudaFuncAttributeMaxDynamicSharedMemorySize, 81920);
        cudaFuncSetAttribute(gemm_out_kernel,    cudaFuncAttributeMaxDynamicSharedMemorySize, 165888);
        cudaFuncSetAttribute(gru_persist_kernel, cudaFuncAttributeMaxDynamicSharedMemorySize, 52736);
        smem_set = 1;
    }

    {
        size_t n4 = (size_t)H3*HH/4;
        f2b_split_kernel<<<(unsigned)((n4+255)/256), 256>>>(W_ih, Wihb, Wihlo, n4);
        f2b_split_kernel<<<(unsigned)((n4+255)/256), 256>>>(W_hh, Whhb, Whhlo, n4);
    }
    {
        size_t n4 = (size_t)VV*HH/4;
        f2b_kernel<<<(unsigned)((n4+255)/256), 256>>>(W_out, Woutb, n4);
    }

    embed_kernel<<<MM, 256>>>(emb, tgt, bos);
    init_h_kernel<<<BB*HH/256, 256>>>(enc_hidden);

    // GI = X @ W_ih^T (compensated)
    gemm_gi_kernel<<<dim3(H3/128, MM/128), 256, 81920>>>(Xb, Xlo, Wihb, Wihlo, GI, H3, HH);

    // persistent GRU: all 64 steps in one launch
    gru_persist_kernel<<<64, 256, 52736>>>(b_ih, b_hh);

    // logits = hs @ W_out^T + b_out -> d_out (remapped to [B,S,V])
    gemm_out_kernel<<<dim3(VV/256, MM/128), 512, 165888>>>(HSb, Woutb, out, b_out, VV, HH);

    // log_softmax in place
    lsm_kernel<<<MM, 256>>>(out);

    // hT tail
    ht_kernel<<<128, 256>>>(out);
}

// round 7
// speedup vs baseline: 1.7656x; 1.2226x over previous
#include <cuda_runtime.h>
#include <cuda_bf16.h>
#include <mma.h>
#include <cstdint>

using namespace nvcuda;

#define VV 32000
#define HH 1024
#define BB 32
#define SS 64
#define H3 3072
#define MM (SS*BB)   // 2048

// tcgen05 availability: host pass keeps the code for syntax; device passes
// without the sm_103a feature (plain compute_103) strip it entirely.
#if !defined(__CUDA_ARCH__) || defined(__CUDA_ARCH_FEAT_SM103_ALL)
#define TC_OK 1
#else
#define TC_OK 0
#endif

// ---------------- scratch ----------------
__device__ __nv_bfloat16 g_Xb[(size_t)MM*HH];
__device__ __nv_bfloat16 g_Xlo[(size_t)MM*HH];
__device__ __nv_bfloat16 g_Wihb[(size_t)H3*HH];
__device__ __nv_bfloat16 g_Wihlo[(size_t)H3*HH];
__device__ __nv_bfloat16 g_Whhb[(size_t)H3*HH];
__device__ __nv_bfloat16 g_Whhlo[(size_t)H3*HH];
__device__ __nv_bfloat16 g_Woutb[(size_t)VV*HH];
__device__ __nv_bfloat16 g_HSb[(size_t)MM*HH];
__device__ float g_GI[(size_t)MM*H3];
__device__ float g_hf[2][BB*HH];
__device__ __nv_bfloat16 g_hhi[2][BB*HH];
__device__ __nv_bfloat16 g_hlo[2][BB*HH];
__device__ int g_bar;

// ---------------- cp.async helpers ----------------
__device__ __forceinline__ uint32_t smem_u32(const void* p){
    return (uint32_t)__cvta_generic_to_shared(p);
}
__device__ __forceinline__ void cp16(void* dst, const void* src){
    asm volatile("cp.async.cg.shared.global [%0], [%1], 16;" :: "r"(smem_u32(dst)), "l"(src));
}
__device__ __forceinline__ void cp16a(uint32_t dst, const void* src){
    asm volatile("cp.async.cg.shared.global [%0], [%1], 16;" :: "r"(dst), "l"(src));
}
__device__ __forceinline__ void cp_commit(){ asm volatile("cp.async.commit_group;"); }
template<int N> __device__ __forceinline__ void cp_wait(){ asm volatile("cp.async.wait_group %0;" :: "n"(N)); }

#define SWZ128(off) ((off) ^ (((off) >> 3) & 0x70))

#if TC_OK
// ---------------- tcgen05 helpers (stripped on non-'a' device pass) ----------------
static __device__ __forceinline__ uint64_t make_desc(uint32_t addr){
    const uint64_t base = (2ULL<<61) | (1ULL<<46) | (64ULL<<32) | (1ULL<<16); // SW128, v1, SBO=64, LBO=1
    return base | (uint64_t)((addr >> 4) & 0x3FFF);
}
__device__ __forceinline__ void mma_f16_ss(uint32_t d, uint64_t ad, uint64_t bd, uint32_t idesc, uint32_t en){
    asm volatile(
        "{\n\t.reg .pred p;\n\t"
        "setp.ne.u32 p, %5, 0;\n\t"
        "tcgen05.mma.cta_group::1.kind::f16 [%0], %1, %2, %3, {%4, %4, %4, %4}, p;\n\t}"
        :: "r"(d), "l"(ad), "l"(bd), "r"(idesc), "r"(0u), "r"(en) : "memory");
}
__device__ __forceinline__ void tc_commit(uint32_t mbar){
    asm volatile("tcgen05.commit.cta_group::1.mbarrier::arrive::one.shared::cluster.b64 [%0];" :: "r"(mbar) : "memory");
}
__device__ __forceinline__ void mbar_init(uint32_t mbar, uint32_t cnt){
    asm volatile("mbarrier.init.shared.b64 [%0], %1;" :: "r"(mbar), "r"(cnt) : "memory");
}
__device__ __forceinline__ void mbar_wait(uint32_t mbar, uint32_t parity){
    asm volatile(
        "{\n\t.reg .pred P1;\n\t"
        "W_%=:\n\t"
        "mbarrier.try_wait.parity.acquire.cta.shared::cta.b64 P1, [%0], %1, 0x989680;\n\t"
        "@!P1 bra.uni W_%=;\n\t}"
        :: "r"(mbar), "r"(parity) : "memory");
}
#define TC_LD_X32(r, a) \
    asm volatile( \
        "tcgen05.ld.sync.aligned.32x32b.x32.b32 " \
        "{%0, %1, %2, %3, %4, %5, %6, %7, " \
        " %8, %9, %10, %11, %12, %13, %14, %15, " \
        " %16, %17, %18, %19, %20, %21, %22, %23, " \
        " %24, %25, %26, %27, %28, %29, %30, %31}, [%32];" \
        : "=r"((r)[0]),  "=r"((r)[1]),  "=r"((r)[2]),  "=r"((r)[3]), \
          "=r"((r)[4]),  "=r"((r)[5]),  "=r"((r)[6]),  "=r"((r)[7]), \
          "=r"((r)[8]),  "=r"((r)[9]),  "=r"((r)[10]), "=r"((r)[11]), \
          "=r"((r)[12]), "=r"((r)[13]), "=r"((r)[14]), "=r"((r)[15]), \
          "=r"((r)[16]), "=r"((r)[17]), "=r"((r)[18]), "=r"((r)[19]), \
          "=r"((r)[20]), "=r"((r)[21]), "=r"((r)[22]), "=r"((r)[23]), \
          "=r"((r)[24]), "=r"((r)[25]), "=r"((r)[26]), "=r"((r)[27]), \
          "=r"((r)[28]), "=r"((r)[29]), "=r"((r)[30]), "=r"((r)[31]) \
        : "r"(a))
#define TC_WAIT_LD()  asm volatile("tcgen05.wait::ld.sync.aligned;" ::: "memory")
#define TC_FENCE_AFTER() asm volatile("tcgen05.fence::after_thread_sync;" ::: "memory")
#endif // TC_OK

// ---------------- fp32 -> bf16 ----------------
__global__ void f2b_kernel(const float* __restrict__ in, __nv_bfloat16* __restrict__ out, size_t n4)
{
    size_t i = (size_t)blockIdx.x * blockDim.x + threadIdx.x;
    if (i >= n4) return;
    float4 v = reinterpret_cast<const float4*>(in)[i];
    reinterpret_cast<__nv_bfloat162*>(out)[2*i]   = __floats2bfloat162_rn(v.x, v.y);
    reinterpret_cast<__nv_bfloat162*>(out)[2*i+1] = __floats2bfloat162_rn(v.z, v.w);
}

// ---------------- fp32 -> bf16 hi/lo split ----------------
__global__ void f2b_split_kernel(const float* __restrict__ in,
                                 __nv_bfloat16* __restrict__ hi,
                                 __nv_bfloat16* __restrict__ lo, size_t n4)
{
    size_t i = (size_t)blockIdx.x * blockDim.x + threadIdx.x;
    if (i >= n4) return;
    float4 v = reinterpret_cast<const float4*>(in)[i];
    float a[4] = {v.x, v.y, v.z, v.w};
    __nv_bfloat16 h[4], l[4];
    #pragma unroll
    for (int k=0;k<4;k++) {
        h[k] = __float2bfloat16(a[k]);
        l[k] = __float2bfloat16(a[k] - __bfloat162float(h[k]));
    }
    reinterpret_cast<__nv_bfloat162*>(hi)[2*i]   = __nv_bfloat162{h[0],h[1]};
    reinterpret_cast<__nv_bfloat162*>(hi)[2*i+1] = __nv_bfloat162{h[2],h[3]};
    reinterpret_cast<__nv_bfloat162*>(lo)[2*i]   = __nv_bfloat162{l[0],l[1]};
    reinterpret_cast<__nv_bfloat162*>(lo)[2*i+1] = __nv_bfloat162{l[2],l[3]};
}

// ---------------- embedding gather + relu -> bf16 hi/lo ----------------
__global__ void embed_kernel(const float* __restrict__ emb, const int* __restrict__ tgt,
                             const int* __restrict__ bos)
{
    int row = blockIdx.x;
    int t = row >> 5, b = row & 31;
    int tok = (t == 0) ? bos[0] : tgt[b*SS + t - 1];
    const float* e = &emb[(size_t)tok * HH];
    for (int i = threadIdx.x; i < HH; i += blockDim.x) {
        float v = e[i];
        v = v > 0.f ? v : 0.f;
        __nv_bfloat16 h = __float2bfloat16(v);
        g_Xb [(size_t)row*HH + i] = h;
        g_Xlo[(size_t)row*HH + i] = __float2bfloat16(v - __bfloat162float(h));
    }
}

// ---------------- init h0 + reset barrier ----------------
__global__ void init_h_kernel(const float* __restrict__ enc)
{
    int i = blockIdx.x*256 + threadIdx.x;
    if (i == 0) g_bar = 0;
    float v = enc[i];
    g_hf[0][i] = v;
    __nv_bfloat16 h = __float2bfloat16(v);
    g_hhi[0][i] = h;
    g_hlo[0][i] = __float2bfloat16(v - __bfloat162float(h));
}

// ================= fused compensated GI GEMM (wmma) =================
__global__ void __launch_bounds__(256) gemm_gi_kernel(
    const __nv_bfloat16* __restrict__ Ah, const __nv_bfloat16* __restrict__ Al,
    const __nv_bfloat16* __restrict__ Bh, const __nv_bfloat16* __restrict__ Bl,
    float* __restrict__ C, int N, int K)
{
    extern __shared__ char dsm[];
    int tid = threadIdx.x, warp = tid >> 5;
    int bm = blockIdx.y * 128, bn = blockIdx.x * 128;
    int wm = (warp >> 1) * 32, wn = (warp & 1) * 64;

    wmma::fragment<wmma::accumulator,16,16,16,float> acc[2][4];
    #pragma unroll
    for (int i=0;i<2;i++)
        #pragma unroll
        for (int j=0;j<4;j++) wmma::fill_fragment(acc[i][j], 0.0f);

    auto stage_ptr = [&](int s, int mat)->__nv_bfloat16* {
        return (__nv_bfloat16*)(dsm + (size_t)s*40960 + (size_t)mat*10240);
    };
    const __nv_bfloat16* srcs[4] = {Ah, Al, Bh, Bl};

    auto prefetch = [&](int s, int kc){
        #pragma unroll
        for (int i=0;i<8;i++){
            int cid = tid + i*256;
            int mat = cid >> 9;
            int k2  = cid & 511;
            int r = k2 >> 2, c = (k2 & 3) * 8;
            int grow = (mat < 2 ? bm : bn) + r;
            cp16(stage_ptr(s,mat) + r*40 + c, srcs[mat] + (size_t)grow*K + kc + c);
        }
        cp_commit();
    };

    const int NIT = K / 32;
    prefetch(0, 0);
    for (int it = 0; it < NIT; ++it){
        int s = it & 1;
        if (it + 1 < NIT){ prefetch(s^1, (it+1)*32); cp_wait<1>(); }
        else cp_wait<0>();
        __syncthreads();
        __nv_bfloat16* SAh = stage_ptr(s,0);
        __nv_bfloat16* SAl = stage_ptr(s,1);
        __nv_bfloat16* SBh = stage_ptr(s,2);
        __nv_bfloat16* SBl = stage_ptr(s,3);
        #pragma unroll
        for (int ks = 0; ks < 2; ks++){
            wmma::fragment<wmma::matrix_a,16,16,16,__nv_bfloat16,wmma::row_major> ah[2], al[2];
            wmma::fragment<wmma::matrix_b,16,16,16,__nv_bfloat16,wmma::col_major> bh[4], bl[4];
            #pragma unroll
            for (int i=0;i<2;i++){
                wmma::load_matrix_sync(ah[i], SAh + (wm+i*16)*40 + ks*16, 40);
                wmma::load_matrix_sync(al[i], SAl + (wm+i*16)*40 + ks*16, 40);
            }
            #pragma unroll
            for (int j=0;j<4;j++){
                wmma::load_matrix_sync(bh[j], SBh + (wn+j*16)*40 + ks*16, 40);
                wmma::load_matrix_sync(bl[j], SBl + (wn+j*16)*40 + ks*16, 40);
            }
            #pragma unroll
            for (int i=0;i<2;i++)
                #pragma unroll
                for (int j=0;j<4;j++){
                    wmma::mma_sync(acc[i][j], ah[i], bh[j], acc[i][j]);
                    wmma::mma_sync(acc[i][j], ah[i], bl[j], acc[i][j]);
                    wmma::mma_sync(acc[i][j], al[i], bh[j], acc[i][j]);
                }
        }
        __syncthreads();
    }
    #pragma unroll
    for (int i=0;i<2;i++)
        #pragma unroll
        for (int j=0;j<4;j++)
            wmma::store_matrix_sync(&C[(size_t)(bm+wm+i*16)*N + bn+wn+j*16],
                                    acc[i][j], N, wmma::mem_row_major);
}

// ================= output GEMM (dual path) =================
// Grid (VV/256, MM/128), 512 threads.
// tcgen05 path: 128x256 C tile = 2 TMEM D-tiles (256 cols), 3-stage cp.async,
//   smem ctrl 1024 + 3 x (A 16K | B 32K) = 148480.
// fallback path (no 'a' target): R4 wmma pipeline, smem 165888.
#define TC_IDESC ((1u<<4)|(1u<<7)|(1u<<10)|(16u<<17)|(8u<<24))   // F32, bf16xbf16, N=128, M=128

__global__ void __launch_bounds__(512) gemm_out_kernel(
    const __nv_bfloat16* __restrict__ A, const __nv_bfloat16* __restrict__ Bm,
    float* __restrict__ C, const float* __restrict__ bias)
{
    extern __shared__ char dsm[];
    int tid = threadIdx.x, warp = tid >> 5, lane = tid & 31;
    int bm = blockIdx.y * 128, bn = blockIdx.x * 256;

#if TC_OK
    uint32_t sb = smem_u32(dsm);

    if (warp == 0)
        asm volatile("tcgen05.alloc.cta_group::1.sync.aligned.shared::cta.b32 [%0], %1;"
                     :: "r"(sb), "r"(256u) : "memory");
    if (tid == 0){
        mbar_init(sb + 8,  1);
        mbar_init(sb + 16, 1);
        mbar_init(sb + 24, 1);
    }
    __syncthreads();
    uint32_t tmem;
    asm volatile("ld.shared.b32 %0, [%1];" : "=r"(tmem) : "r"(sb));

    // stage s at sb+1024+s*49152: A[128x128B] then B[256x128B]
    auto prefetch = [&](int j){
        uint32_t so = sb + 1024 + (uint32_t)(j % 3) * 49152u;
        int kc = j * 64;
        #pragma unroll
        for (int i=0;i<6;i++){
            int cid = tid + i*512;               // 0..3071
            if (cid < 1024){                     // A: 128 rows x 8 16B chunks
                int r = cid >> 3, c16 = cid & 7;
                uint32_t off = (uint32_t)(r*128 + c16*16);
                cp16a(so + SWZ128(off), A + (size_t)(bm + r)*HH + kc + c16*8);
            } else {                             // B: 256 rows x 8
                int q = cid - 1024;
                int r = q >> 3, c16 = q & 7;
                uint32_t off = (uint32_t)(r*128 + c16*16);
                cp16a(so + 16384u + SWZ128(off), Bm + (size_t)(bn + r)*HH + kc + c16*8);
            }
        }
        cp_commit();
    };

    const int NCH = HH / 64;   // 16
    prefetch(0);
    prefetch(1);
    for (int i = 0; i < NCH; ++i){
        int s = i % 3;
        if (i + 2 < NCH){
            if (i >= 1) mbar_wait(sb + 8 + 8*((i-1)%3), (uint32_t)(((i-1)/3) & 1));
            prefetch(i + 2);
            cp_wait<2>();
        } else if (i + 1 < NCH) cp_wait<1>();
        else cp_wait<0>();
        asm volatile("fence.proxy.async.shared::cta;" ::: "memory");
        __syncthreads();

        if (tid == 0){
            uint32_t so = sb + 1024 + (uint32_t)s * 49152u;
            uint64_t ad = make_desc(so);
            uint64_t b0 = make_desc(so + 16384u);
            uint64_t b1 = make_desc(so + 32768u);
            #pragma unroll
            for (int ks = 0; ks < 4; ks++){
                uint64_t off = (uint64_t)(ks * 2);
                uint32_t en = (i > 0 || ks > 0) ? 1u : 0u;
                mma_f16_ss(tmem +   0, ad + off, b0 + off, TC_IDESC, en);
                mma_f16_ss(tmem + 128, ad + off, b1 + off, TC_IDESC, en);
            }
            tc_commit(sb + 8 + 8*s);
        }
        __syncthreads();
    }

    // wait for the last chunks' MMA commits (stages 1,2,0 from chunks 13,14,15)
    mbar_wait(sb + 16, 0);   // chunk 13 (stage 1, 5th completion -> parity 0)
    mbar_wait(sb + 24, 0);   // chunk 14 (stage 2)
    mbar_wait(sb + 8,  1);   // chunk 15 (stage 0, 6th completion -> parity 1)
    TC_FENCE_AFTER();

    // epilogue: warp w -> rows (w&3)*32+lane, D-tile (w>>2)&1, col-half (w>>3)
    {
        int rowgrp = warp & 3, ti = (warp >> 2) & 1, ch = warp >> 3;
        int gr = bm + rowgrp*32 + lane;              // GEMM row = t*B + b
        int orow = (gr & 31) * SS + (gr >> 5);       // [B,S] remap
        float* op = C + (size_t)orow * VV + bn + ti*128 + ch*64;
        const float* bp = bias + bn + ti*128 + ch*64;
        #pragma unroll
        for (int cc = 0; cc < 2; cc++){
            uint32_t d[32];
            TC_LD_X32(d, tmem + ti*128 + ch*64 + cc*32);
            TC_WAIT_LD();
            #pragma unroll
            for (int q = 0; q < 8; q++){
                float4 v;
                v.x = __uint_as_float(d[q*4+0]) + bp[cc*32 + q*4 + 0];
                v.y = __uint_as_float(d[q*4+1]) + bp[cc*32 + q*4 + 1];
                v.z = __uint_as_float(d[q*4+2]) + bp[cc*32 + q*4 + 2];
                v.w = __uint_as_float(d[q*4+3]) + bp[cc*32 + q*4 + 3];
                *reinterpret_cast<float4*>(op + cc*32 + q*4) = v;
            }
        }
    }

    __syncthreads();
    if (warp == 0){
        asm volatile("tcgen05.relinquish_alloc_permit.cta_group::1.sync.aligned;");
        asm volatile("tcgen05.dealloc.cta_group::1.sync.aligned.b32 %0, %1;" :: "r"(tmem), "r"(256u));
    }
#else
    // ---------- fallback: wmma 3-stage pipeline (R4-proven) ----------
    int wm = (warp >> 2) * 32;
    int wn = (warp & 3) * 64;

    wmma::fragment<wmma::accumulator,16,16,16,float> acc[2][4];
    #pragma unroll
    for (int i=0;i<2;i++)
        #pragma unroll
        for (int j=0;j<4;j++) wmma::fill_fragment(acc[i][j], 0.0f);

    auto SA = [&](int s)->__nv_bfloat16* { return (__nv_bfloat16*)(dsm + (size_t)s*55296); };
    auto SB = [&](int s)->__nv_bfloat16* { return (__nv_bfloat16*)(dsm + (size_t)s*55296 + 18432); };

    auto prefetch = [&](int s, int kc){
        #pragma unroll
        for (int i=0;i<6;i++){
            int cid = tid + i*512;
            if (cid < 1024){
                int r = cid >> 3, c = (cid & 7) * 8;
                cp16(SA(s) + r*72 + c, A + (size_t)(bm+r)*HH + kc + c);
            } else {
                int k2 = cid - 1024;
                int r = k2 >> 3, c = (k2 & 7) * 8;
                cp16(SB(s) + r*72 + c, Bm + (size_t)(bn+r)*HH + kc + c);
            }
        }
        cp_commit();
    };

    const int NIT = HH / 64;
    prefetch(0, 0);
    prefetch(1, 64);
    for (int it = 0; it < NIT; ++it){
        int s = it % 3;
        if (it + 2 < NIT){ prefetch((it+2)%3, (it+2)*64); cp_wait<2>(); }
        else if (it + 1 < NIT) cp_wait<1>();
        else cp_wait<0>();
        __syncthreads();
        #pragma unroll
        for (int ks = 0; ks < 4; ks++){
            wmma::fragment<wmma::matrix_a,16,16,16,__nv_bfloat16,wmma::row_major> af[2];
            wmma::fragment<wmma::matrix_b,16,16,16,__nv_bfloat16,wmma::col_major> bf[4];
            #pragma unroll
            for (int i=0;i<2;i++) wmma::load_matrix_sync(af[i], SA(s) + (wm+i*16)*72 + ks*16, 72);
            #pragma unroll
            for (int j=0;j<4;j++) wmma::load_matrix_sync(bf[j], SB(s) + (wn+j*16)*72 + ks*16, 72);
            #pragma unroll
            for (int i=0;i<2;i++)
                #pragma unroll
                for (int j=0;j<4;j++)
                    wmma::mma_sync(acc[i][j], af[i], bf[j], acc[i][j]);
        }
        __syncthreads();
    }

    float* CS = (float*)dsm;
    #pragma unroll
    for (int i=0;i<2;i++){
        #pragma unroll
        for (int j=0;j<4;j++){
            wmma::store_matrix_sync(CS + warp*256, acc[i][j], 16, wmma::mem_row_major);
            __syncwarp();
            #pragma unroll
            for (int e=0;e<8;e++){
                int idx = lane*8 + e;
                int r = idx >> 4, c = idx & 15;
                int gr = bm + wm + i*16 + r;
                int gc = bn + wn + j*16 + c;
                float v = CS[warp*256 + idx] + bias[gc];
                int orow = (gr & 31) * SS + (gr >> 5);
                C[(size_t)orow * VV + gc] = v;
            }
            __syncwarp();
        }
    }
#endif
}

// ================= persistent GRU kernel (all 64 steps, 64 blocks) =================
__global__ void __launch_bounds__(256) gru_persist_kernel(
    const float* __restrict__ bih, const float* __restrict__ bhh)
{
    extern __shared__ char dsm[];
    int tid = threadIdx.x, warp = tid >> 5;
    int j0 = blockIdx.x * 16;

    auto SHh = [&](int s)->__nv_bfloat16* { return (__nv_bfloat16*)(dsm + (size_t)s*23040); };
    auto SHl = [&](int s)->__nv_bfloat16* { return (__nv_bfloat16*)(dsm + (size_t)s*23040 + 4608); };
    auto SWh = [&](int s)->__nv_bfloat16* { return (__nv_bfloat16*)(dsm + (size_t)s*23040 + 9216); };
    auto SWl = [&](int s)->__nv_bfloat16* { return (__nv_bfloat16*)(dsm + (size_t)s*23040 + 16128); };
    float* CS = (float*)(dsm + 46080);

    int mi = warp & 1, ni = warp >> 1;

    for (int t = 0; t < SS; ++t){
        int cur = t & 1, nxt = cur ^ 1;
        const __nv_bfloat16* hhi = g_hhi[cur];
        const __nv_bfloat16* hlo = g_hlo[cur];

        wmma::fragment<wmma::accumulator,16,16,16,float> acc;
        wmma::fill_fragment(acc, 0.0f);

        auto prefetch = [&](int s, int kc){
            #pragma unroll
            for (int i=0;i<5;i++){
                int cid = tid + i*256;
                if (cid < 512){
                    int mat = cid >> 8, k2 = cid & 255;
                    int r = k2 >> 3, c = (k2 & 7) * 8;
                    const __nv_bfloat16* src = (mat ? hlo : hhi) + r*HH + kc + c;
                    __nv_bfloat16* dst = (mat ? SHl(s) : SHh(s)) + r*72 + c;
                    cp16(dst, src);
                } else {
                    int k2 = cid - 512;
                    int mat = k2 >= 384; if (mat) k2 -= 384;
                    int r = k2 >> 3, c = (k2 & 7) * 8;
                    int wrow = (r >> 4) * HH + j0 + (r & 15);
                    const __nv_bfloat16* src = (mat ? g_Whhlo : g_Whhb) + (size_t)wrow*HH + kc + c;
                    __nv_bfloat16* dst = (mat ? SWl(s) : SWh(s)) + r*72 + c;
                    cp16(dst, src);
                }
            }
            cp_commit();
        };

        const int NIT = HH / 64;
        prefetch(0, 0);
        for (int it = 0; it < NIT; ++it){
            int s = it & 1;
            if (it + 1 < NIT){ prefetch(s^1, (it+1)*64); cp_wait<1>(); }
            else cp_wait<0>();
            __syncthreads();
            if (warp < 6){
                #pragma unroll
                for (int ks = 0; ks < 4; ks++){
                    wmma::fragment<wmma::matrix_a,16,16,16,__nv_bfloat16,wmma::row_major> ah, al;
                    wmma::fragment<wmma::matrix_b,16,16,16,__nv_bfloat16,wmma::col_major> bh, bl;
                    wmma::load_matrix_sync(ah, SHh(s) + (mi*16)*72 + ks*16, 72);
                    wmma::load_matrix_sync(al, SHl(s) + (mi*16)*72 + ks*16, 72);
                    wmma::load_matrix_sync(bh, SWh(s) + (ni*16)*72 + ks*16, 72);
                    wmma::load_matrix_sync(bl, SWl(s) + (ni*16)*72 + ks*16, 72);
                    wmma::mma_sync(acc, ah, bh, acc);
                    wmma::mma_sync(acc, ah, bl, acc);
                    wmma::mma_sync(acc, al, bh, acc);
                }
            }
            __syncthreads();
        }

        if (warp < 6)
            wmma::store_matrix_sync(CS + (mi*16)*52 + ni*16, acc, 52, wmma::mem_row_major);
        __syncthreads();

        #pragma unroll
        for (int e = tid; e < 512; e += 256){
            int b = e >> 4, jl = e & 15;
            int j = j0 + jl;
            float ghr = CS[b*52 + jl];
            float ghz = CS[b*52 + 16 + jl];
            float ghn = CS[b*52 + 32 + jl];
            const float* gi = &g_GI[(size_t)(t*BB + b)*H3];
            float gir = gi[j]        + bih[j];
            float giz = gi[HH + j]   + bih[HH + j];
            float gin = gi[2*HH + j] + bih[2*HH + j];
            float r = 1.f/(1.f + expf(-(gir + ghr + bhh[j])));
            float z = 1.f/(1.f + expf(-(giz + ghz + bhh[HH + j])));
            float n = tanhf(gin + r*(ghn + bhh[2*HH + j]));
            float h = (1.f - z)*n + z*g_hf[cur][b*HH + j];
            g_hf[nxt][b*HH + j] = h;
            __nv_bfloat16 hb = __float2bfloat16(h);
            g_hhi[nxt][b*HH + j] = hb;
            g_hlo[nxt][b*HH + j] = __float2bfloat16(h - __bfloat162float(hb));
            g_HSb[(size_t)(t*BB + b)*HH + j] = hb;
        }

        __threadfence();
        __syncthreads();
        if (tid == 0){
            atomicAdd(&g_bar, 1);
            int target = 64 * (t + 1);
            while (*(volatile int*)&g_bar < target) { }
        }
        __syncthreads();
    }
}

// ---------------- log_softmax in place (online, 2 passes) ----------------
__global__ void lsm_kernel(float* __restrict__ out)
{
    __shared__ float rm[256], rs[256];
    float4* p = (float4*)(out + (size_t)blockIdx.x * VV);
    float m = -1e30f, s = 0.f;
    for (int i = threadIdx.x; i < 8000; i += 256){
        float4 v = p[i];
        float a[4] = {v.x, v.y, v.z, v.w};
        #pragma unroll
        for (int k=0;k<4;k++){
            float x = a[k];
            if (x > m){ s = s * expf(m - x) + 1.f; m = x; }
            else s += expf(x - m);
        }
    }
    rm[threadIdx.x] = m; rs[threadIdx.x] = s; __syncthreads();
    for (int st=128; st>0; st>>=1){
        if (threadIdx.x < st){
            float m2 = rm[threadIdx.x+st], s2 = rs[threadIdx.x+st];
            float m1 = rm[threadIdx.x],    s1 = rs[threadIdx.x];
            float M = fmaxf(m1, m2);
            rm[threadIdx.x] = M;
            rs[threadIdx.x] = s1 * expf(m1 - M) + s2 * expf(m2 - M);
        }
        __syncthreads();
    }
    float lse = rm[0] + logf(rs[0]);
    for (int i = threadIdx.x; i < 8000; i += 256){
        float4 v = p[i];
        v.x -= lse; v.y -= lse; v.z -= lse; v.w -= lse;
        p[i] = v;
    }
}

// ---------------- hT tail ----------------
__global__ void ht_kernel(float* __restrict__ out)
{
    int i = blockIdx.x*blockDim.x + threadIdx.x;
    if (i < BB*HH) out[(size_t)BB*SS*VV + i] = g_hf[0][i];
}

// ---------------- launch ----------------
extern "C" void kernel_launch(void* const* d_in, const int* in_sizes, int n_in,
                              void* d_out, int out_size)
{
    const float* enc_hidden = (const float*)d_in[1];
    const int*   bos        = (const int*)  d_in[2];
    const int*   tgt        = (const int*)  d_in[3];
    const float* emb        = (const float*)d_in[4];
    const float* W_ih       = (const float*)d_in[5];
    const float* W_hh       = (const float*)d_in[6];
    const float* b_ih       = (const float*)d_in[7];
    const float* b_hh       = (const float*)d_in[8];
    const float* W_out      = (const float*)d_in[9];
    const float* b_out      = (const float*)d_in[10];
    float* out = (float*)d_out;

    __nv_bfloat16 *Xb, *Xlo, *Wihb, *Wihlo, *Whhb, *Whhlo, *Woutb, *HSb;
    float *GI;
    cudaGetSymbolAddress((void**)&Xb,    g_Xb);
    cudaGetSymbolAddress((void**)&Xlo,   g_Xlo);
    cudaGetSymbolAddress((void**)&Wihb,  g_Wihb);
    cudaGetSymbolAddress((void**)&Wihlo, g_Wihlo);
    cudaGetSymbolAddress((void**)&Whhb,  g_Whhb);
    cudaGetSymbolAddress((void**)&Whhlo, g_Whhlo);
    cudaGetSymbolAddress((void**)&Woutb, g_Woutb);
    cudaGetSymbolAddress((void**)&HSb,   g_HSb);
    cudaGetSymbolAddress((void**)&GI,    g_GI);

    static int smem_set = 0;
    if (!smem_set){
        cudaFuncSetAttribute(gemm_gi_kernel,     cudaFuncAttributeMaxDynamicSharedMemorySize, 81920);
        cudaFuncSetAttribute(gemm_out_kernel,    cudaFuncAttributeMaxDynamicSharedMemorySize, 165888);
        cudaFuncSetAttribute(gru_persist_kernel, cudaFuncAttributeMaxDynamicSharedMemorySize, 52736);
        smem_set = 1;
    }

    {
        size_t n4 = (size_t)H3*HH/4;
        f2b_split_kernel<<<(unsigned)((n4+255)/256), 256>>>(W_ih, Wihb, Wihlo, n4);
        f2b_split_kernel<<<(unsigned)((n4+255)/256), 256>>>(W_hh, Whhb, Whhlo, n4);
    }
    {
        size_t n4 = (size_t)VV*HH/4;
        f2b_kernel<<<(unsigned)((n4+255)/256), 256>>>(W_out, Woutb, n4);
    }

    embed_kernel<<<MM, 256>>>(emb, tgt, bos);
    init_h_kernel<<<BB*HH/256, 256>>>(enc_hidden);

    gemm_gi_kernel<<<dim3(H3/128, MM/128), 256, 81920>>>(Xb, Xlo, Wihb, Wihlo, GI, H3, HH);

    gru_persist_kernel<<<64, 256, 52736>>>(b_ih, b_hh);

    // output GEMM (tcgen05 on sm_103a cubin, wmma fallback otherwise)
    gemm_out_kernel<<<dim3(VV/256, MM/128), 512, 165888>>>(HSb, Woutb, out, b_out);

    lsm_kernel<<<MM, 256>>>(out);
    ht_kernel<<<128, 256>>>(out);
}

// round 9
// speedup vs baseline: 2.0480x; 1.1600x over previous
#include <cuda_runtime.h>
#include <cuda_bf16.h>
#include <mma.h>
#include <cstdint>

using namespace nvcuda;

#define VV 32000
#define HH 1024
#define BB 32
#define SS 64
#define H3 3072
#define MM (SS*BB)   // 2048

#if !defined(__CUDA_ARCH__) || defined(__CUDA_ARCH_FEAT_SM103_ALL)
#define TC_OK 1
#else
#define TC_OK 0
#endif

// ---------------- scratch ----------------
__device__ __nv_bfloat16 g_Xb[(size_t)MM*HH];
__device__ __nv_bfloat16 g_Xlo[(size_t)MM*HH];
__device__ __nv_bfloat16 g_Wihb[(size_t)H3*HH];
__device__ __nv_bfloat16 g_Wihlo[(size_t)H3*HH];
__device__ __nv_bfloat16 g_Whhb[(size_t)H3*HH];
__device__ __nv_bfloat16 g_Whhlo[(size_t)H3*HH];
__device__ __nv_bfloat16 g_Woutb[(size_t)VV*HH];
__device__ __nv_bfloat16 g_HSb[(size_t)MM*HH];
__device__ float g_GI[(size_t)MM*H3];
__device__ float g_hf[2][BB*HH];
__device__ __nv_bfloat16 g_hhi[2][BB*HH];
__device__ __nv_bfloat16 g_hlo[2][BB*HH];
__device__ int g_bar;

// ---------------- cp.async helpers ----------------
__device__ __forceinline__ uint32_t smem_u32(const void* p){
    return (uint32_t)__cvta_generic_to_shared(p);
}
__device__ __forceinline__ void cp16(void* dst, const void* src){
    asm volatile("cp.async.cg.shared.global [%0], [%1], 16;" :: "r"(smem_u32(dst)), "l"(src));
}
__device__ __forceinline__ void cp16a(uint32_t dst, const void* src){
    asm volatile("cp.async.cg.shared.global [%0], [%1], 16;" :: "r"(dst), "l"(src));
}
__device__ __forceinline__ void cp_commit(){ asm volatile("cp.async.commit_group;"); }
template<int N> __device__ __forceinline__ void cp_wait(){ asm volatile("cp.async.wait_group %0;" :: "n"(N)); }

#define SWZ128(off) ((off) ^ (((off) >> 3) & 0x70))

#if TC_OK
// ---------------- tcgen05 helpers ----------------
static __device__ __forceinline__ uint64_t make_desc(uint32_t addr){
    const uint64_t base = (2ULL<<61) | (1ULL<<46) | (64ULL<<32) | (1ULL<<16); // SW128, v1, SBO=64, LBO=1
    return base | (uint64_t)((addr >> 4) & 0x3FFF);
}
__device__ __forceinline__ void mma_f16_ss(uint32_t d, uint64_t ad, uint64_t bd, uint32_t idesc, uint32_t en){
    asm volatile(
        "{\n\t.reg .pred p;\n\t"
        "setp.ne.u32 p, %5, 0;\n\t"
        "tcgen05.mma.cta_group::1.kind::f16 [%0], %1, %2, %3, {%4, %4, %4, %4}, p;\n\t}"
        :: "r"(d), "l"(ad), "l"(bd), "r"(idesc), "r"(0u), "r"(en) : "memory");
}
__device__ __forceinline__ void tc_commit(uint32_t mbar){
    asm volatile("tcgen05.commit.cta_group::1.mbarrier::arrive::one.shared::cluster.b64 [%0];" :: "r"(mbar) : "memory");
}
__device__ __forceinline__ void mbar_init(uint32_t mbar, uint32_t cnt){
    asm volatile("mbarrier.init.shared.b64 [%0], %1;" :: "r"(mbar), "r"(cnt) : "memory");
}
__device__ __forceinline__ void mbar_wait(uint32_t mbar, uint32_t parity){
    asm volatile(
        "{\n\t.reg .pred P1;\n\t"
        "W_%=:\n\t"
        "mbarrier.try_wait.parity.acquire.cta.shared::cta.b64 P1, [%0], %1, 0x989680;\n\t"
        "@!P1 bra.uni W_%=;\n\t}"
        :: "r"(mbar), "r"(parity) : "memory");
}
#define TC_LD_X32(r, a) \
    asm volatile( \
        "tcgen05.ld.sync.aligned.32x32b.x32.b32 " \
        "{%0, %1, %2, %3, %4, %5, %6, %7, " \
        " %8, %9, %10, %11, %12, %13, %14, %15, " \
        " %16, %17, %18, %19, %20, %21, %22, %23, " \
        " %24, %25, %26, %27, %28, %29, %30, %31}, [%32];" \
        : "=r"((r)[0]),  "=r"((r)[1]),  "=r"((r)[2]),  "=r"((r)[3]), \
          "=r"((r)[4]),  "=r"((r)[5]),  "=r"((r)[6]),  "=r"((r)[7]), \
          "=r"((r)[8]),  "=r"((r)[9]),  "=r"((r)[10]), "=r"((r)[11]), \
          "=r"((r)[12]), "=r"((r)[13]), "=r"((r)[14]), "=r"((r)[15]), \
          "=r"((r)[16]), "=r"((r)[17]), "=r"((r)[18]), "=r"((r)[19]), \
          "=r"((r)[20]), "=r"((r)[21]), "=r"((r)[22]), "=r"((r)[23]), \
          "=r"((r)[24]), "=r"((r)[25]), "=r"((r)[26]), "=r"((r)[27]), \
          "=r"((r)[28]), "=r"((r)[29]), "=r"((r)[30]), "=r"((r)[31]) \
        : "r"(a))
#define TC_WAIT_LD()  asm volatile("tcgen05.wait::ld.sync.aligned;" ::: "memory")
#define TC_FENCE_AFTER() asm volatile("tcgen05.fence::after_thread_sync;" ::: "memory")
#endif // TC_OK

// ---------------- fp32 -> bf16 ----------------
__global__ void f2b_kernel(const float* __restrict__ in, __nv_bfloat16* __restrict__ out, size_t n4)
{
    size_t i = (size_t)blockIdx.x * blockDim.x + threadIdx.x;
    if (i >= n4) return;
    float4 v = reinterpret_cast<const float4*>(in)[i];
    reinterpret_cast<__nv_bfloat162*>(out)[2*i]   = __floats2bfloat162_rn(v.x, v.y);
    reinterpret_cast<__nv_bfloat162*>(out)[2*i+1] = __floats2bfloat162_rn(v.z, v.w);
}

// ---------------- fp32 -> bf16 hi/lo split ----------------
__global__ void f2b_split_kernel(const float* __restrict__ in,
                                 __nv_bfloat16* __restrict__ hi,
                                 __nv_bfloat16* __restrict__ lo, size_t n4)
{
    size_t i = (size_t)blockIdx.x * blockDim.x + threadIdx.x;
    if (i >= n4) return;
    float4 v = reinterpret_cast<const float4*>(in)[i];
    float a[4] = {v.x, v.y, v.z, v.w};
    __nv_bfloat16 h[4], l[4];
    #pragma unroll
    for (int k=0;k<4;k++) {
        h[k] = __float2bfloat16(a[k]);
        l[k] = __float2bfloat16(a[k] - __bfloat162float(h[k]));
    }
    reinterpret_cast<__nv_bfloat162*>(hi)[2*i]   = __nv_bfloat162{h[0],h[1]};
    reinterpret_cast<__nv_bfloat162*>(hi)[2*i+1] = __nv_bfloat162{h[2],h[3]};
    reinterpret_cast<__nv_bfloat162*>(lo)[2*i]   = __nv_bfloat162{l[0],l[1]};
    reinterpret_cast<__nv_bfloat162*>(lo)[2*i+1] = __nv_bfloat162{l[2],l[3]};
}

// ---------------- embedding gather + relu -> bf16 hi/lo ----------------
__global__ void embed_kernel(const float* __restrict__ emb, const int* __restrict__ tgt,
                             const int* __restrict__ bos)
{
    int row = blockIdx.x;
    int t = row >> 5, b = row & 31;
    int tok = (t == 0) ? bos[0] : tgt[b*SS + t - 1];
    const float* e = &emb[(size_t)tok * HH];
    for (int i = threadIdx.x; i < HH; i += blockDim.x) {
        float v = e[i];
        v = v > 0.f ? v : 0.f;
        __nv_bfloat16 h = __float2bfloat16(v);
        g_Xb [(size_t)row*HH + i] = h;
        g_Xlo[(size_t)row*HH + i] = __float2bfloat16(v - __bfloat162float(h));
    }
}

// ---------------- init h0 + reset barrier ----------------
__global__ void init_h_kernel(const float* __restrict__ enc)
{
    int i = blockIdx.x*256 + threadIdx.x;
    if (i == 0) g_bar = 0;
    float v = enc[i];
    g_hf[0][i] = v;
    __nv_bfloat16 h = __float2bfloat16(v);
    g_hhi[0][i] = h;
    g_hlo[0][i] = __float2bfloat16(v - __bfloat162float(h));
}

// ================= GI GEMM: tcgen05 3-term compensated =================
// GI[2048,3072] = (Xh+Xl) @ (Wh+Wl)^T  (3 terms). Grid (H3/256=12, MM/128=16), 256 thr.
// CTA tile 128x256 -> 2 TMEM D-tiles (256 cols). 2-stage, stage=96KB: Ah|Al|Bh|Bl.
#define TC_IDESC ((1u<<4)|(1u<<7)|(1u<<10)|(16u<<17)|(8u<<24))   // F32, bf16xbf16, N=128, M=128

__global__ void __launch_bounds__(256) gemm_gi_kernel(
    const __nv_bfloat16* __restrict__ Ah, const __nv_bfloat16* __restrict__ Al,
    const __nv_bfloat16* __restrict__ Bh, const __nv_bfloat16* __restrict__ Bl,
    float* __restrict__ C)
{
    extern __shared__ char dsm[];
    int tid = threadIdx.x, warp = tid >> 5, lane = tid & 31;
    int bm = blockIdx.y * 128, bn = blockIdx.x * 256;

#if TC_OK
    uint32_t sb = smem_u32(dsm);
    if (warp == 0)
        asm volatile("tcgen05.alloc.cta_group::1.sync.aligned.shared::cta.b32 [%0], %1;"
                     :: "r"(sb), "r"(256u) : "memory");
    if (tid == 0){ mbar_init(sb + 8, 1); mbar_init(sb + 16, 1); }
    __syncthreads();
    uint32_t tmem;
    asm volatile("ld.shared.b32 %0, [%1];" : "=r"(tmem) : "r"(sb));

    // stage s at sb+1024+s*98304: Ah 16K | Al 16K | Bh 32K | Bl 32K
    auto prefetch = [&](int j){
        uint32_t so = sb + 1024 + (uint32_t)(j & 1) * 98304u;
        int kc = j * 64;
        #pragma unroll
        for (int i=0;i<24;i++){
            int cid = tid + i*256;                // 0..6143
            if (cid < 2048){                      // A hi/lo: 2 x 128 rows x 8
                int mat = cid >> 10, k2 = cid & 1023;
                int r = k2 >> 3, c16 = k2 & 7;
                uint32_t off = (uint32_t)(r*128 + c16*16);
                const __nv_bfloat16* src = (mat ? Al : Ah) + (size_t)(bm + r)*HH + kc + c16*8;
                cp16a(so + (uint32_t)mat*16384u + SWZ128(off), src);
            } else {                              // B hi/lo: 2 x 256 rows x 8
                int q = cid - 2048;
                int mat = q >> 11, k2 = q & 2047;
                int r = k2 >> 3, c16 = k2 & 7;
                uint32_t off = (uint32_t)(r*128 + c16*16);
                const __nv_bfloat16* src = (mat ? Bl : Bh) + (size_t)(bn + r)*HH + kc + c16*8;
                cp16a(so + 32768u + (uint32_t)mat*32768u + SWZ128(off), src);
            }
        }
        cp_commit();
    };

    const int NCH = HH / 64;   // 16
    prefetch(0);
    for (int i = 0; i < NCH; ++i){
        int s = i & 1;
        if (i + 1 < NCH){
            if (i >= 1) mbar_wait(sb + 8 + 8*((i-1)&1), (uint32_t)(((i-1)>>1) & 1));
            prefetch(i + 1);
            cp_wait<1>();
        } else cp_wait<0>();
        asm volatile("fence.proxy.async.shared::cta;" ::: "memory");
        __syncthreads();

        if (tid == 0){
            uint32_t so = sb + 1024 + (uint32_t)s * 98304u;
            uint64_t ahd = make_desc(so);
            uint64_t ald = make_desc(so + 16384u);
            uint64_t bh0 = make_desc(so + 32768u);
            uint64_t bh1 = make_desc(so + 49152u);
            uint64_t bl0 = make_desc(so + 65536u);
            uint64_t bl1 = make_desc(so + 81920u);
            #pragma unroll
            for (int ks = 0; ks < 4; ks++){
                uint64_t off = (uint64_t)(ks * 2);
                uint32_t en = (i > 0 || ks > 0) ? 1u : 0u;
                mma_f16_ss(tmem +   0, ahd + off, bh0 + off, TC_IDESC, en);
                mma_f16_ss(tmem +   0, ahd + off, bl0 + off, TC_IDESC, 1u);
                mma_f16_ss(tmem +   0, ald + off, bh0 + off, TC_IDESC, 1u);
                mma_f16_ss(tmem + 128, ahd + off, bh1 + off, TC_IDESC, en);
                mma_f16_ss(tmem + 128, ahd + off, bl1 + off, TC_IDESC, 1u);
                mma_f16_ss(tmem + 128, ald + off, bh1 + off, TC_IDESC, 1u);
            }
            tc_commit(sb + 8 + 8*s);
        }
        __syncthreads();
    }

    mbar_wait(sb + 8,  1);   // stage 0 last: chunk 14 (completion 7 -> parity 1)
    mbar_wait(sb + 16, 1);   // stage 1 last: chunk 15
    TC_FENCE_AFTER();

    // epilogue: 8 warps = 2 N-tiles x 4 rowgroups
    {
        int rowgrp = warp & 3, ni = warp >> 2;
        int gr = bm + rowgrp*32 + lane;
        float* op = C + (size_t)gr * H3 + bn + ni*128;
        #pragma unroll
        for (int cc = 0; cc < 4; cc++){
            uint32_t d[32];
            TC_LD_X32(d, tmem + ni*128 + cc*32);
            TC_WAIT_LD();
            #pragma unroll
            for (int q = 0; q < 8; q++){
                float4 v;
                v.x = __uint_as_float(d[q*4+0]);
                v.y = __uint_as_float(d[q*4+1]);
                v.z = __uint_as_float(d[q*4+2]);
                v.w = __uint_as_float(d[q*4+3]);
                *reinterpret_cast<float4*>(op + cc*32 + q*4) = v;
            }
        }
    }

    __syncthreads();
    if (warp == 0){
        asm volatile("tcgen05.relinquish_alloc_permit.cta_group::1.sync.aligned;");
        asm volatile("tcgen05.dealloc.cta_group::1.sync.aligned.b32 %0, %1;" :: "r"(tmem), "r"(256u));
    }
#else
    // correct-but-slow canary fallback (never selected on GB300)
    for (int e = tid; e < 128*256; e += 256){
        int r = e >> 8, c = e & 255;
        float acc = 0.f;
        for (int k = 0; k < HH; k++){
            float ah = __bfloat162float(Ah[(size_t)(bm+r)*HH+k]);
            float al = __bfloat162float(Al[(size_t)(bm+r)*HH+k]);
            float bh = __bfloat162float(Bh[(size_t)(bn+c)*HH+k]);
            float bl = __bfloat162float(Bl[(size_t)(bn+c)*HH+k]);
            acc += ah*bh + ah*bl + al*bh;
        }
        C[(size_t)(bm+r)*H3 + bn + c] = acc;
    }
#endif
}

// ================= output GEMM: tcgen05 256x256 =================
// Grid (MM/256=8, VV/256=125): consecutive CTAs share the B slice (L2 reuse).
// 4 TMEM D-tiles (512 cols), 3-stage, stage=64KB: A0 16K | A1 16K | B 32K.
__global__ void __launch_bounds__(512) gemm_out_kernel(
    const __nv_bfloat16* __restrict__ A, const __nv_bfloat16* __restrict__ Bm,
    float* __restrict__ C, const float* __restrict__ bias)
{
    extern __shared__ char dsm[];
    int tid = threadIdx.x, warp = tid >> 5, lane = tid & 31;
    int bm = blockIdx.x * 256, bn = blockIdx.y * 256;

#if TC_OK
    uint32_t sb = smem_u32(dsm);
    if (warp == 0)
        asm volatile("tcgen05.alloc.cta_group::1.sync.aligned.shared::cta.b32 [%0], %1;"
                     :: "r"(sb), "r"(512u) : "memory");
    if (tid == 0){ mbar_init(sb + 8, 1); mbar_init(sb + 16, 1); mbar_init(sb + 24, 1); }
    __syncthreads();
    uint32_t tmem;
    asm volatile("ld.shared.b32 %0, [%1];" : "=r"(tmem) : "r"(sb));

    auto prefetch = [&](int j){
        uint32_t so = sb + 1024 + (uint32_t)(j % 3) * 65536u;
        int kc = j * 64;
        #pragma unroll
        for (int i=0;i<8;i++){
            int cid = tid + i*512;                // 0..4095
            if (cid < 2048){                      // A: 256 rows x 8
                int r = cid >> 3, c16 = cid & 7;
                int tile = r >> 7, rr = r & 127;
                uint32_t off = (uint32_t)(rr*128 + c16*16);
                cp16a(so + (uint32_t)tile*16384u + SWZ128(off),
                      A + (size_t)(bm + r)*HH + kc + c16*8);
            } else {                              // B: 256 rows x 8
                int q = cid - 2048;
                int r = q >> 3, c16 = q & 7;
                uint32_t off = (uint32_t)(r*128 + c16*16);
                cp16a(so + 32768u + SWZ128(off),
                      Bm + (size_t)(bn + r)*HH + kc + c16*8);
            }
        }
        cp_commit();
    };

    const int NCH = HH / 64;   // 16
    prefetch(0);
    prefetch(1);
    for (int i = 0; i < NCH; ++i){
        int s = i % 3;
        if (i + 2 < NCH){
            if (i >= 1) mbar_wait(sb + 8 + 8*((i-1)%3), (uint32_t)(((i-1)/3) & 1));
            prefetch(i + 2);
            cp_wait<2>();
        } else if (i + 1 < NCH) cp_wait<1>();
        else cp_wait<0>();
        asm volatile("fence.proxy.async.shared::cta;" ::: "memory");
        __syncthreads();

        if (tid == 0){
            uint32_t so = sb + 1024 + (uint32_t)s * 65536u;
            uint64_t a0 = make_desc(so);
            uint64_t a1 = make_desc(so + 16384u);
            uint64_t b0 = make_desc(so + 32768u);
            uint64_t b1 = make_desc(so + 49152u);
            #pragma unroll
            for (int ks = 0; ks < 4; ks++){
                uint64_t off = (uint64_t)(ks * 2);
                uint32_t en = (i > 0 || ks > 0) ? 1u : 0u;
                mma_f16_ss(tmem +   0, a0 + off, b0 + off, TC_IDESC, en);
                mma_f16_ss(tmem + 128, a0 + off, b1 + off, TC_IDESC, en);
                mma_f16_ss(tmem + 256, a1 + off, b0 + off, TC_IDESC, en);
                mma_f16_ss(tmem + 384, a1 + off, b1 + off, TC_IDESC, en);
            }
            tc_commit(sb + 8 + 8*s);
        }
        __syncthreads();
    }

    mbar_wait(sb + 16, 0);   // chunk 13 (stage 1, completion 4 -> parity 0)
    mbar_wait(sb + 24, 0);   // chunk 14 (stage 2)
    mbar_wait(sb + 8,  1);   // chunk 15 (stage 0, completion 5 -> parity 1)
    TC_FENCE_AFTER();

    // epilogue: 16 warps = 4 D-tiles x 4 rowgroups
    {
        int rowgrp = warp & 3, tile = warp >> 2;   // tile = mi*2+ni
        int mi = tile >> 1, ni = tile & 1;
        int gr = bm + mi*128 + rowgrp*32 + lane;   // GEMM row = t*B + b
        int orow = (gr & 31) * SS + (gr >> 5);     // [B,S] remap
        float* op = C + (size_t)orow * VV + bn + ni*128;
        const float* bp = bias + bn + ni*128;
        #pragma unroll
        for (int cc = 0; cc < 4; cc++){
            uint32_t d[32];
            TC_LD_X32(d, tmem + tile*128 + cc*32);
            TC_WAIT_LD();
            #pragma unroll
            for (int q = 0; q < 8; q++){
                float4 v;
                v.x = __uint_as_float(d[q*4+0]) + bp[cc*32 + q*4 + 0];
                v.y = __uint_as_float(d[q*4+1]) + bp[cc*32 + q*4 + 1];
                v.z = __uint_as_float(d[q*4+2]) + bp[cc*32 + q*4 + 2];
                v.w = __uint_as_float(d[q*4+3]) + bp[cc*32 + q*4 + 3];
                *reinterpret_cast<float4*>(op + cc*32 + q*4) = v;
            }
        }
    }

    __syncthreads();
    if (warp == 0){
        asm volatile("tcgen05.relinquish_alloc_permit.cta_group::1.sync.aligned;");
        asm volatile("tcgen05.dealloc.cta_group::1.sync.aligned.b32 %0, %1;" :: "r"(tmem), "r"(512u));
    }
#else
    // correct-but-slow canary fallback
    for (int e = tid; e < 256*256; e += 512){
        int r = e >> 8, c = e & 255;
        float acc = bias[bn + c];
        for (int k = 0; k < HH; k++)
            acc += __bfloat162float(A[(size_t)(bm+r)*HH+k]) *
                   __bfloat162float(Bm[(size_t)(bn+c)*HH+k]);
        int gr = bm + r;
        int orow = (gr & 31) * SS + (gr >> 5);
        C[(size_t)orow * VV + bn + c] = acc;
    }
#endif
}

// ================= persistent GRU kernel: W_hh resident in SMEM =================
// 64 blocks, 256 thr. Block owns j-tile of 16 (48 W rows x 1024 K, hi+lo).
// SMEM: Wh [0,100608) stride 1048 el (conflict-free), Wl [100608,201216),
//       stages at 201216: 2 x (SHh 4608 | SHl 4608) = 18432. CS aliased at 201216.
#define WST 1048

__global__ void __launch_bounds__(256) gru_persist_kernel(
    const float* __restrict__ bih, const float* __restrict__ bhh)
{
    extern __shared__ char dsm[];
    int tid = threadIdx.x, warp = tid >> 5;
    int j0 = blockIdx.x * 16;

    __nv_bfloat16* Wh = (__nv_bfloat16*)dsm;
    __nv_bfloat16* Wl = Wh + 48*WST;          // +50304 elements = 100608 B
    char* stbase = dsm + 201216;
    auto SHh = [&](int s)->__nv_bfloat16* { return (__nv_bfloat16*)(stbase + s*9216); };
    auto SHl = [&](int s)->__nv_bfloat16* { return (__nv_bfloat16*)(stbase + s*9216 + 4608); };
    float* CS = (float*)stbase;               // aliased after mma loop

    // ---- W preload (once): 12288 cp16 ----
    #pragma unroll
    for (int i=0;i<48;i++){
        int cid = tid + i*256;                // 0..12287
        int mat = cid >= 6144;
        int k2 = mat ? cid - 6144 : cid;
        int r = k2 >> 7, c16 = k2 & 127;      // 48 rows x 128 chunks
        int wrow = (r >> 4)*HH + j0 + (r & 15);
        const __nv_bfloat16* src = (mat ? g_Whhlo : g_Whhb) + (size_t)wrow*HH + c16*8;
        __nv_bfloat16* dst = (mat ? Wl : Wh) + r*WST + c16*8;
        cp16(dst, src);
    }
    cp_commit(); cp_wait<0>(); __syncthreads();

    int mi = warp & 1, ni = warp >> 1;

    for (int t = 0; t < SS; ++t){
        int cur = t & 1, nxt = cur ^ 1;
        const __nv_bfloat16* hhi = g_hhi[cur];
        const __nv_bfloat16* hlo = g_hlo[cur];

        wmma::fragment<wmma::accumulator,16,16,16,float> acc;
        wmma::fill_fragment(acc, 0.0f);

        auto prefetch = [&](int s, int kc){
            #pragma unroll
            for (int i=0;i<2;i++){
                int cid = tid + i*256;        // 0..511
                int mat = cid >> 8, k2 = cid & 255;
                int r = k2 >> 3, c = (k2 & 7) * 8;   // 32 rows x 8 chunks (64 cols)
                const __nv_bfloat16* src = (mat ? hlo : hhi) + r*HH + kc + c;
                __nv_bfloat16* dst = (mat ? SHl(s) : SHh(s)) + r*72 + c;
                cp16(dst, src);
            }
            cp_commit();
        };

        const int NIT = HH / 64;   // 16
        prefetch(0, 0);
        for (int it = 0; it < NIT; ++it){
            int s = it & 1;
            if (it + 1 < NIT){ prefetch(s^1, (it+1)*64); cp_wait<1>(); }
            else cp_wait<0>();
            __syncthreads();
            if (warp < 6){
                #pragma unroll
                for (int ks = 0; ks < 4; ks++){
                    wmma::fragment<wmma::matrix_a,16,16,16,__nv_bfloat16,wmma::row_major> ah, al;
                    wmma::fragment<wmma::matrix_b,16,16,16,__nv_bfloat16,wmma::col_major> bh, bl;
                    wmma::load_matrix_sync(ah, SHh(s) + (mi*16)*72 + ks*16, 72);
                    wmma::load_matrix_sync(al, SHl(s) + (mi*16)*72 + ks*16, 72);
                    wmma::load_matrix_sync(bh, Wh + (ni*16)*WST + it*64 + ks*16, WST);
                    wmma::load_matrix_sync(bl, Wl + (ni*16)*WST + it*64 + ks*16, WST);
                    wmma::mma_sync(acc, ah, bh, acc);
                    wmma::mma_sync(acc, ah, bl, acc);
                    wmma::mma_sync(acc, al, bh, acc);
                }
            }
            __syncthreads();
        }

        if (warp < 6)
            wmma::store_matrix_sync(CS + (mi*16)*52 + ni*16, acc, 52, wmma::mem_row_major);
        __syncthreads();

        #pragma unroll
        for (int e = tid; e < 512; e += 256){
            int b = e >> 4, jl = e & 15;
            int j = j0 + jl;
            float ghr = CS[b*52 + jl];
            float ghz = CS[b*52 + 16 + jl];
            float ghn = CS[b*52 + 32 + jl];
            const float* gi = &g_GI[(size_t)(t*BB + b)*H3];
            float gir = gi[j]        + bih[j];
            float giz = gi[HH + j]   + bih[HH + j];
            float gin = gi[2*HH + j] + bih[2*HH + j];
            float r = 1.f/(1.f + expf(-(gir + ghr + bhh[j])));
            float z = 1.f/(1.f + expf(-(giz + ghz + bhh[HH + j])));
            float n = tanhf(gin + r*(ghn + bhh[2*HH + j]));
            float h = (1.f - z)*n + z*g_hf[cur][b*HH + j];
            g_hf[nxt][b*HH + j] = h;
            __nv_bfloat16 hb = __float2bfloat16(h);
            g_hhi[nxt][b*HH + j] = hb;
            g_hlo[nxt][b*HH + j] = __float2bfloat16(h - __bfloat162float(hb));
            g_HSb[(size_t)(t*BB + b)*HH + j] = hb;
        }

        __threadfence();
        __syncthreads();
        if (tid == 0){
            atomicAdd(&g_bar, 1);
            int target = 64 * (t + 1);
            while (*(volatile int*)&g_bar < target) { }
        }
        __syncthreads();
    }
}

// ---------------- log_softmax in place (online, 2 passes) ----------------
__global__ void lsm_kernel(float* __restrict__ out)
{
    __shared__ float rm[256], rs[256];
    float4* p = (float4*)(out + (size_t)blockIdx.x * VV);
    float m = -1e30f, s = 0.f;
    for (int i = threadIdx.x; i < 8000; i += 256){
        float4 v = p[i];
        float a[4] = {v.x, v.y, v.z, v.w};
        #pragma unroll
        for (int k=0;k<4;k++){
            float x = a[k];
            if (x > m){ s = s * expf(m - x) + 1.f; m = x; }
            else s += expf(x - m);
        }
    }
    rm[threadIdx.x] = m; rs[threadIdx.x] = s; __syncthreads();
    for (int st=128; st>0; st>>=1){
        if (threadIdx.x < st){
            float m2 = rm[threadIdx.x+st], s2 = rs[threadIdx.x+st];
            float m1 = rm[threadIdx.x],    s1 = rs[threadIdx.x];
            float M = fmaxf(m1, m2);
            rm[threadIdx.x] = M;
            rs[threadIdx.x] = s1 * expf(m1 - M) + s2 * expf(m2 - M);
        }
        __syncthreads();
    }
    float lse = rm[0] + logf(rs[0]);
    for (int i = threadIdx.x; i < 8000; i += 256){
        float4 v = p[i];
        v.x -= lse; v.y -= lse; v.z -= lse; v.w -= lse;
        p[i] = v;
    }
}

// ---------------- hT tail ----------------
__global__ void ht_kernel(float* __restrict__ out)
{
    int i = blockIdx.x*blockDim.x + threadIdx.x;
    if (i < BB*HH) out[(size_t)BB*SS*VV + i] = g_hf[0][i];
}

// ---------------- launch ----------------
extern "C" void kernel_launch(void* const* d_in, const int* in_sizes, int n_in,
                              void* d_out, int out_size)
{
    const float* enc_hidden = (const float*)d_in[1];
    const int*   bos        = (const int*)  d_in[2];
    const int*   tgt        = (const int*)  d_in[3];
    const float* emb        = (const float*)d_in[4];
    const float* W_ih       = (const float*)d_in[5];
    const float* W_hh       = (const float*)d_in[6];
    const float* b_ih       = (const float*)d_in[7];
    const float* b_hh       = (const float*)d_in[8];
    const float* W_out      = (const float*)d_in[9];
    const float* b_out      = (const float*)d_in[10];
    float* out = (float*)d_out;

    __nv_bfloat16 *Xb, *Xlo, *Wihb, *Wihlo, *Whhb, *Whhlo, *Woutb, *HSb;
    float *GI;
    cudaGetSymbolAddress((void**)&Xb,    g_Xb);
    cudaGetSymbolAddress((void**)&Xlo,   g_Xlo);
    cudaGetSymbolAddress((void**)&Wihb,  g_Wihb);
    cudaGetSymbolAddress((void**)&Wihlo, g_Wihlo);
    cudaGetSymbolAddress((void**)&Whhb,  g_Whhb);
    cudaGetSymbolAddress((void**)&Whhlo, g_Whhlo);
    cudaGetSymbolAddress((void**)&Woutb, g_Woutb);
    cudaGetSymbolAddress((void**)&HSb,   g_HSb);
    cudaGetSymbolAddress((void**)&GI,    g_GI);

    static int smem_set = 0;
    if (!smem_set){
        cudaFuncSetAttribute(gemm_gi_kernel,     cudaFuncAttributeMaxDynamicSharedMemorySize, 197632);
        cudaFuncSetAttribute(gemm_out_kernel,    cudaFuncAttributeMaxDynamicSharedMemorySize, 197632);
        cudaFuncSetAttribute(gru_persist_kernel, cudaFuncAttributeMaxDynamicSharedMemorySize, 219648);
        smem_set = 1;
    }

    {
        size_t n4 = (size_t)H3*HH/4;
        f2b_split_kernel<<<(unsigned)((n4+255)/256), 256>>>(W_ih, Wihb, Wihlo, n4);
        f2b_split_kernel<<<(unsigned)((n4+255)/256), 256>>>(W_hh, Whhb, Whhlo, n4);
    }
    {
        size_t n4 = (size_t)VV*HH/4;
        f2b_kernel<<<(unsigned)((n4+255)/256), 256>>>(W_out, Woutb, n4);
    }

    embed_kernel<<<MM, 256>>>(emb, tgt, bos);
    init_h_kernel<<<BB*HH/256, 256>>>(enc_hidden);

    // GI = X @ W_ih^T (compensated, tcgen05)
    gemm_gi_kernel<<<dim3(H3/256, MM/128), 256, 197632>>>(Xb, Xlo, Wihb, Wihlo, GI);

    // persistent GRU (W_hh resident in SMEM)
    gru_persist_kernel<<<64, 256, 219648>>>(b_ih, b_hh);

    // logits = hs @ W_out^T + b_out (tcgen05 256x256, B-sharing grid order)
    gemm_out_kernel<<<dim3(MM/256, VV/256), 512, 197632>>>(HSb, Woutb, out, b_out);

    lsm_kernel<<<MM, 256>>>(out);
    ht_kernel<<<128, 256>>>(out);
}

// round 10
// speedup vs baseline: 2.4572x; 1.1998x over previous
#include <cuda_runtime.h>
#include <cuda_bf16.h>
#include <mma.h>
#include <cstdint>

using namespace nvcuda;

#define VV 32000
#define HH 1024
#define BB 32
#define SS 64
#define H3 3072
#define MM (SS*BB)   // 2048

#if !defined(__CUDA_ARCH__) || defined(__CUDA_ARCH_FEAT_SM103_ALL)
#define TC_OK 1
#else
#define TC_OK 0
#endif

// ---------------- scratch ----------------
__device__ __nv_bfloat16 g_Xb[(size_t)MM*HH];
__device__ __nv_bfloat16 g_Xlo[(size_t)MM*HH];
__device__ __nv_bfloat16 g_Wihb[(size_t)H3*HH];
__device__ __nv_bfloat16 g_Wihlo[(size_t)H3*HH];
__device__ __nv_bfloat16 g_Whhb[(size_t)H3*HH];
__device__ __nv_bfloat16 g_Whhlo[(size_t)H3*HH];
__device__ __nv_bfloat16 g_Woutb[(size_t)VV*HH];
__device__ __nv_bfloat16 g_HSb[(size_t)MM*HH];
__device__ float g_GI[(size_t)MM*H3];
__device__ float g_hf[2][BB*HH];
__device__ __nv_bfloat16 g_hhi[2][BB*HH];
__device__ __nv_bfloat16 g_hlo[2][BB*HH];
__device__ int g_bar;

// ---------------- cp.async helpers ----------------
__device__ __forceinline__ uint32_t smem_u32(const void* p){
    return (uint32_t)__cvta_generic_to_shared(p);
}
__device__ __forceinline__ void cp16(void* dst, const void* src){
    asm volatile("cp.async.cg.shared.global [%0], [%1], 16;" :: "r"(smem_u32(dst)), "l"(src));
}
__device__ __forceinline__ void cp16a(uint32_t dst, const void* src){
    asm volatile("cp.async.cg.shared.global [%0], [%1], 16;" :: "r"(dst), "l"(src));
}
__device__ __forceinline__ void cp_commit(){ asm volatile("cp.async.commit_group;"); }
template<int N> __device__ __forceinline__ void cp_wait(){ asm volatile("cp.async.wait_group %0;" :: "n"(N)); }

#define SWZ128(off) ((off) ^ (((off) >> 3) & 0x70))

#if TC_OK
// ---------------- tcgen05 helpers ----------------
static __device__ __forceinline__ uint64_t make_desc(uint32_t addr){
    const uint64_t base = (2ULL<<61) | (1ULL<<46) | (64ULL<<32) | (1ULL<<16); // SW128, v1, SBO=64, LBO=1
    return base | (uint64_t)((addr >> 4) & 0x3FFF);
}
__device__ __forceinline__ void mma_f16_ss(uint32_t d, uint64_t ad, uint64_t bd, uint32_t idesc, uint32_t en){
    asm volatile(
        "{\n\t.reg .pred p;\n\t"
        "setp.ne.u32 p, %5, 0;\n\t"
        "tcgen05.mma.cta_group::1.kind::f16 [%0], %1, %2, %3, {%4, %4, %4, %4}, p;\n\t}"
        :: "r"(d), "l"(ad), "l"(bd), "r"(idesc), "r"(0u), "r"(en) : "memory");
}
__device__ __forceinline__ void tc_commit(uint32_t mbar){
    asm volatile("tcgen05.commit.cta_group::1.mbarrier::arrive::one.shared::cluster.b64 [%0];" :: "r"(mbar) : "memory");
}
__device__ __forceinline__ void mbar_init(uint32_t mbar, uint32_t cnt){
    asm volatile("mbarrier.init.shared.b64 [%0], %1;" :: "r"(mbar), "r"(cnt) : "memory");
}
__device__ __forceinline__ void mbar_wait(uint32_t mbar, uint32_t parity){
    asm volatile(
        "{\n\t.reg .pred P1;\n\t"
        "W_%=:\n\t"
        "mbarrier.try_wait.parity.acquire.cta.shared::cta.b64 P1, [%0], %1, 0x989680;\n\t"
        "@!P1 bra.uni W_%=;\n\t}"
        :: "r"(mbar), "r"(parity) : "memory");
}
#define TC_LD_X32(r, a) \
    asm volatile( \
        "tcgen05.ld.sync.aligned.32x32b.x32.b32 " \
        "{%0, %1, %2, %3, %4, %5, %6, %7, " \
        " %8, %9, %10, %11, %12, %13, %14, %15, " \
        " %16, %17, %18, %19, %20, %21, %22, %23, " \
        " %24, %25, %26, %27, %28, %29, %30, %31}, [%32];" \
        : "=r"((r)[0]),  "=r"((r)[1]),  "=r"((r)[2]),  "=r"((r)[3]), \
          "=r"((r)[4]),  "=r"((r)[5]),  "=r"((r)[6]),  "=r"((r)[7]), \
          "=r"((r)[8]),  "=r"((r)[9]),  "=r"((r)[10]), "=r"((r)[11]), \
          "=r"((r)[12]), "=r"((r)[13]), "=r"((r)[14]), "=r"((r)[15]), \
          "=r"((r)[16]), "=r"((r)[17]), "=r"((r)[18]), "=r"((r)[19]), \
          "=r"((r)[20]), "=r"((r)[21]), "=r"((r)[22]), "=r"((r)[23]), \
          "=r"((r)[24]), "=r"((r)[25]), "=r"((r)[26]), "=r"((r)[27]), \
          "=r"((r)[28]), "=r"((r)[29]), "=r"((r)[30]), "=r"((r)[31]) \
        : "r"(a))
#define TC_WAIT_LD()  asm volatile("tcgen05.wait::ld.sync.aligned;" ::: "memory")
#define TC_FENCE_AFTER() asm volatile("tcgen05.fence::after_thread_sync;" ::: "memory")
#endif // TC_OK

// ---------------- fp32 -> bf16 ----------------
__global__ void f2b_kernel(const float* __restrict__ in, __nv_bfloat16* __restrict__ out, size_t n4)
{
    size_t i = (size_t)blockIdx.x * blockDim.x + threadIdx.x;
    if (i >= n4) return;
    float4 v = reinterpret_cast<const float4*>(in)[i];
    reinterpret_cast<__nv_bfloat162*>(out)[2*i]   = __floats2bfloat162_rn(v.x, v.y);
    reinterpret_cast<__nv_bfloat162*>(out)[2*i+1] = __floats2bfloat162_rn(v.z, v.w);
}

// ---------------- fp32 -> bf16 hi/lo split ----------------
__global__ void f2b_split_kernel(const float* __restrict__ in,
                                 __nv_bfloat16* __restrict__ hi,
                                 __nv_bfloat16* __restrict__ lo, size_t n4)
{
    size_t i = (size_t)blockIdx.x * blockDim.x + threadIdx.x;
    if (i >= n4) return;
    float4 v = reinterpret_cast<const float4*>(in)[i];
    float a[4] = {v.x, v.y, v.z, v.w};
    __nv_bfloat16 h[4], l[4];
    #pragma unroll
    for (int k=0;k<4;k++) {
        h[k] = __float2bfloat16(a[k]);
        l[k] = __float2bfloat16(a[k] - __bfloat162float(h[k]));
    }
    reinterpret_cast<__nv_bfloat162*>(hi)[2*i]   = __nv_bfloat162{h[0],h[1]};
    reinterpret_cast<__nv_bfloat162*>(hi)[2*i+1] = __nv_bfloat162{h[2],h[3]};
    reinterpret_cast<__nv_bfloat162*>(lo)[2*i]   = __nv_bfloat162{l[0],l[1]};
    reinterpret_cast<__nv_bfloat162*>(lo)[2*i+1] = __nv_bfloat162{l[2],l[3]};
}

// ---------------- embedding gather + relu -> bf16 hi/lo ----------------
__global__ void embed_kernel(const float* __restrict__ emb, const int* __restrict__ tgt,
                             const int* __restrict__ bos)
{
    int row = blockIdx.x;
    int t = row >> 5, b = row & 31;
    int tok = (t == 0) ? bos[0] : tgt[b*SS + t - 1];
    const float* e = &emb[(size_t)tok * HH];
    for (int i = threadIdx.x; i < HH; i += blockDim.x) {
        float v = e[i];
        v = v > 0.f ? v : 0.f;
        __nv_bfloat16 h = __float2bfloat16(v);
        g_Xb [(size_t)row*HH + i] = h;
        g_Xlo[(size_t)row*HH + i] = __float2bfloat16(v - __bfloat162float(h));
    }
}

// ---------------- init h0 + reset barrier ----------------
__global__ void init_h_kernel(const float* __restrict__ enc)
{
    int i = blockIdx.x*256 + threadIdx.x;
    if (i == 0) g_bar = 0;
    float v = enc[i];
    g_hf[0][i] = v;
    __nv_bfloat16 h = __float2bfloat16(v);
    g_hhi[0][i] = h;
    g_hlo[0][i] = __float2bfloat16(v - __bfloat162float(h));
}

// ================= GI GEMM: tcgen05 3-term compensated =================
#define TC_IDESC ((1u<<4)|(1u<<7)|(1u<<10)|(16u<<17)|(8u<<24))   // F32, bf16xbf16, N=128, M=128

__global__ void __launch_bounds__(256) gemm_gi_kernel(
    const __nv_bfloat16* __restrict__ Ah, const __nv_bfloat16* __restrict__ Al,
    const __nv_bfloat16* __restrict__ Bh, const __nv_bfloat16* __restrict__ Bl,
    float* __restrict__ C)
{
    extern __shared__ char dsm[];
    int tid = threadIdx.x, warp = tid >> 5, lane = tid & 31;
    int bm = blockIdx.y * 128, bn = blockIdx.x * 256;

#if TC_OK
    uint32_t sb = smem_u32(dsm);
    if (warp == 0)
        asm volatile("tcgen05.alloc.cta_group::1.sync.aligned.shared::cta.b32 [%0], %1;"
                     :: "r"(sb), "r"(256u) : "memory");
    if (tid == 0){ mbar_init(sb + 8, 1); mbar_init(sb + 16, 1); }
    __syncthreads();
    uint32_t tmem;
    asm volatile("ld.shared.b32 %0, [%1];" : "=r"(tmem) : "r"(sb));

    auto prefetch = [&](int j){
        uint32_t so = sb + 1024 + (uint32_t)(j & 1) * 98304u;
        int kc = j * 64;
        #pragma unroll
        for (int i=0;i<24;i++){
            int cid = tid + i*256;
            if (cid < 2048){
                int mat = cid >> 10, k2 = cid & 1023;
                int r = k2 >> 3, c16 = k2 & 7;
                uint32_t off = (uint32_t)(r*128 + c16*16);
                const __nv_bfloat16* src = (mat ? Al : Ah) + (size_t)(bm + r)*HH + kc + c16*8;
                cp16a(so + (uint32_t)mat*16384u + SWZ128(off), src);
            } else {
                int q = cid - 2048;
                int mat = q >> 11, k2 = q & 2047;
                int r = k2 >> 3, c16 = k2 & 7;
                uint32_t off = (uint32_t)(r*128 + c16*16);
                const __nv_bfloat16* src = (mat ? Bl : Bh) + (size_t)(bn + r)*HH + kc + c16*8;
                cp16a(so + 32768u + (uint32_t)mat*32768u + SWZ128(off), src);
            }
        }
        cp_commit();
    };

    const int NCH = HH / 64;   // 16
    prefetch(0);
    for (int i = 0; i < NCH; ++i){
        int s = i & 1;
        if (i + 1 < NCH){
            if (i >= 1) mbar_wait(sb + 8 + 8*((i-1)&1), (uint32_t)(((i-1)>>1) & 1));
            prefetch(i + 1);
            cp_wait<1>();
        } else cp_wait<0>();
        asm volatile("fence.proxy.async.shared::cta;" ::: "memory");
        __syncthreads();

        if (tid == 0){
            uint32_t so = sb + 1024 + (uint32_t)s * 98304u;
            uint64_t ahd = make_desc(so);
            uint64_t ald = make_desc(so + 16384u);
            uint64_t bh0 = make_desc(so + 32768u);
            uint64_t bh1 = make_desc(so + 49152u);
            uint64_t bl0 = make_desc(so + 65536u);
            uint64_t bl1 = make_desc(so + 81920u);
            #pragma unroll
            for (int ks = 0; ks < 4; ks++){
                uint64_t off = (uint64_t)(ks * 2);
                uint32_t en = (i > 0 || ks > 0) ? 1u : 0u;
                mma_f16_ss(tmem +   0, ahd + off, bh0 + off, TC_IDESC, en);
                mma_f16_ss(tmem +   0, ahd + off, bl0 + off, TC_IDESC, 1u);
                mma_f16_ss(tmem +   0, ald + off, bh0 + off, TC_IDESC, 1u);
                mma_f16_ss(tmem + 128, ahd + off, bh1 + off, TC_IDESC, en);
                mma_f16_ss(tmem + 128, ahd + off, bl1 + off, TC_IDESC, 1u);
                mma_f16_ss(tmem + 128, ald + off, bh1 + off, TC_IDESC, 1u);
            }
            tc_commit(sb + 8 + 8*s);
        }
        __syncthreads();
    }

    mbar_wait(sb + 8,  1);
    mbar_wait(sb + 16, 1);
    TC_FENCE_AFTER();

    {
        int rowgrp = warp & 3, ni = warp >> 2;
        int gr = bm + rowgrp*32 + lane;
        float* op = C + (size_t)gr * H3 + bn + ni*128;
        #pragma unroll
        for (int cc = 0; cc < 4; cc++){
            uint32_t d[32];
            TC_LD_X32(d, tmem + ni*128 + cc*32);
            TC_WAIT_LD();
            #pragma unroll
            for (int q = 0; q < 8; q++){
                float4 v;
                v.x = __uint_as_float(d[q*4+0]);
                v.y = __uint_as_float(d[q*4+1]);
                v.z = __uint_as_float(d[q*4+2]);
                v.w = __uint_as_float(d[q*4+3]);
                *reinterpret_cast<float4*>(op + cc*32 + q*4) = v;
            }
        }
    }

    __syncthreads();
    if (warp == 0){
        asm volatile("tcgen05.relinquish_alloc_permit.cta_group::1.sync.aligned;");
        asm volatile("tcgen05.dealloc.cta_group::1.sync.aligned.b32 %0, %1;" :: "r"(tmem), "r"(256u));
    }
#else
    for (int e = tid; e < 128*256; e += 256){
        int r = e >> 8, c = e & 255;
        float acc = 0.f;
        for (int k = 0; k < HH; k++){
            float ah = __bfloat162float(Ah[(size_t)(bm+r)*HH+k]);
            float al = __bfloat162float(Al[(size_t)(bm+r)*HH+k]);
            float bh = __bfloat162float(Bh[(size_t)(bn+c)*HH+k]);
            float bl = __bfloat162float(Bl[(size_t)(bn+c)*HH+k]);
            acc += ah*bh + ah*bl + al*bh;
        }
        C[(size_t)(bm+r)*H3 + bn + c] = acc;
    }
#endif
}

// ================= output GEMM: tcgen05 256x256 =================
__global__ void __launch_bounds__(512) gemm_out_kernel(
    const __nv_bfloat16* __restrict__ A, const __nv_bfloat16* __restrict__ Bm,
    float* __restrict__ C, const float* __restrict__ bias)
{
    extern __shared__ char dsm[];
    int tid = threadIdx.x, warp = tid >> 5, lane = tid & 31;
    int bm = blockIdx.x * 256, bn = blockIdx.y * 256;

#if TC_OK
    uint32_t sb = smem_u32(dsm);
    if (warp == 0)
        asm volatile("tcgen05.alloc.cta_group::1.sync.aligned.shared::cta.b32 [%0], %1;"
                     :: "r"(sb), "r"(512u) : "memory");
    if (tid == 0){ mbar_init(sb + 8, 1); mbar_init(sb + 16, 1); mbar_init(sb + 24, 1); }
    __syncthreads();
    uint32_t tmem;
    asm volatile("ld.shared.b32 %0, [%1];" : "=r"(tmem) : "r"(sb));

    auto prefetch = [&](int j){
        uint32_t so = sb + 1024 + (uint32_t)(j % 3) * 65536u;
        int kc = j * 64;
        #pragma unroll
        for (int i=0;i<8;i++){
            int cid = tid + i*512;
            if (cid < 2048){
                int r = cid >> 3, c16 = cid & 7;
                int tile = r >> 7, rr = r & 127;
                uint32_t off = (uint32_t)(rr*128 + c16*16);
                cp16a(so + (uint32_t)tile*16384u + SWZ128(off),
                      A + (size_t)(bm + r)*HH + kc + c16*8);
            } else {
                int q = cid - 2048;
                int r = q >> 3, c16 = q & 7;
                uint32_t off = (uint32_t)(r*128 + c16*16);
                cp16a(so + 32768u + SWZ128(off),
                      Bm + (size_t)(bn + r)*HH + kc + c16*8);
            }
        }
        cp_commit();
    };

    const int NCH = HH / 64;   // 16
    prefetch(0);
    prefetch(1);
    for (int i = 0; i < NCH; ++i){
        int s = i % 3;
        if (i + 2 < NCH){
            if (i >= 1) mbar_wait(sb + 8 + 8*((i-1)%3), (uint32_t)(((i-1)/3) & 1));
            prefetch(i + 2);
            cp_wait<2>();
        } else if (i + 1 < NCH) cp_wait<1>();
        else cp_wait<0>();
        asm volatile("fence.proxy.async.shared::cta;" ::: "memory");
        __syncthreads();

        if (tid == 0){
            uint32_t so = sb + 1024 + (uint32_t)s * 65536u;
            uint64_t a0 = make_desc(so);
            uint64_t a1 = make_desc(so + 16384u);
            uint64_t b0 = make_desc(so + 32768u);
            uint64_t b1 = make_desc(so + 49152u);
            #pragma unroll
            for (int ks = 0; ks < 4; ks++){
                uint64_t off = (uint64_t)(ks * 2);
                uint32_t en = (i > 0 || ks > 0) ? 1u : 0u;
                mma_f16_ss(tmem +   0, a0 + off, b0 + off, TC_IDESC, en);
                mma_f16_ss(tmem + 128, a0 + off, b1 + off, TC_IDESC, en);
                mma_f16_ss(tmem + 256, a1 + off, b0 + off, TC_IDESC, en);
                mma_f16_ss(tmem + 384, a1 + off, b1 + off, TC_IDESC, en);
            }
            tc_commit(sb + 8 + 8*s);
        }
        __syncthreads();
    }

    mbar_wait(sb + 16, 0);
    mbar_wait(sb + 24, 0);
    mbar_wait(sb + 8,  1);
    TC_FENCE_AFTER();

    {
        int rowgrp = warp & 3, tile = warp >> 2;
        int mi = tile >> 1, ni = tile & 1;
        int gr = bm + mi*128 + rowgrp*32 + lane;
        int orow = (gr & 31) * SS + (gr >> 5);
        float* op = C + (size_t)orow * VV + bn + ni*128;
        const float* bp = bias + bn + ni*128;
        #pragma unroll
        for (int cc = 0; cc < 4; cc++){
            uint32_t d[32];
            TC_LD_X32(d, tmem + tile*128 + cc*32);
            TC_WAIT_LD();
            #pragma unroll
            for (int q = 0; q < 8; q++){
                float4 v;
                v.x = __uint_as_float(d[q*4+0]) + bp[cc*32 + q*4 + 0];
                v.y = __uint_as_float(d[q*4+1]) + bp[cc*32 + q*4 + 1];
                v.z = __uint_as_float(d[q*4+2]) + bp[cc*32 + q*4 + 2];
                v.w = __uint_as_float(d[q*4+3]) + bp[cc*32 + q*4 + 3];
                *reinterpret_cast<float4*>(op + cc*32 + q*4) = v;
            }
        }
    }

    __syncthreads();
    if (warp == 0){
        asm volatile("tcgen05.relinquish_alloc_permit.cta_group::1.sync.aligned;");
        asm volatile("tcgen05.dealloc.cta_group::1.sync.aligned.b32 %0, %1;" :: "r"(tmem), "r"(512u));
    }
#else
    for (int e = tid; e < 256*256; e += 512){
        int r = e >> 8, c = e & 255;
        float acc = bias[bn + c];
        for (int k = 0; k < HH; k++)
            acc += __bfloat162float(A[(size_t)(bm+r)*HH+k]) *
                   __bfloat162float(Bm[(size_t)(bn+c)*HH+k]);
        int gr = bm + r;
        int orow = (gr & 31) * SS + (gr >> 5);
        C[(size_t)orow * VV + bn + c] = acc;
    }
#endif
}

// ================= persistent GRU: W + full-h resident, sync-free K loop =================
// 128 blocks, 256 thr (8 warps). Block owns j-tile of 8 (24 W rows hi+lo resident).
// Per step: load ALL of h (hi+lo, 32x1024 each) into SMEM once, then each warp runs
// its K-split MMA loop with no block syncs. 2 rotating accumulators break the chain.
// SMEM (element stride 1032 bf16 = 2064B, odd 16B-bank stride -> conflict-free):
//   Wh [0, 49536)  Wl [49536, 99072)  Hh [99072, 165120)  Hl [165120, 231168)
//   CS aliases Hh after compute (8 warps x 256 floats = 8192B).
#define JT 8
#define WSTE 1032
#define GRU_BLOCKS 128
#define GRU_SMEM 231168

__global__ void __launch_bounds__(256) gru_persist_kernel(
    const float* __restrict__ bih, const float* __restrict__ bhh)
{
    extern __shared__ char dsm[];
    int tid = threadIdx.x, warp = tid >> 5;
    int j0 = blockIdx.x * JT;

    __nv_bfloat16* Wh = (__nv_bfloat16*)dsm;
    __nv_bfloat16* Wl = Wh + 24*WSTE;
    __nv_bfloat16* Hh = (__nv_bfloat16*)(dsm + 99072);
    __nv_bfloat16* Hl = (__nv_bfloat16*)(dsm + 165120);
    float* CS = (float*)(dsm + 99072);   // aliases Hh after compute

    // ---- W preload (once): 24 rows x 128 chunks x 2 mats = 6144 cp16 ----
    #pragma unroll
    for (int i=0;i<24;i++){
        int cid = tid + i*256;               // 0..6143
        int mat = cid >= 3072;
        int k2 = mat ? cid - 3072 : cid;
        int r = k2 >> 7, c16 = k2 & 127;     // 24 rows x 128 chunks
        int wrow = (r >> 3)*HH + j0 + (r & 7);
        const __nv_bfloat16* src = (mat ? g_Whhlo : g_Whhb) + (size_t)wrow*HH + c16*8;
        __nv_bfloat16* dst = (mat ? Wl : Wh) + r*WSTE + c16*8;
        cp16(dst, src);
    }
    cp_commit(); cp_wait<0>(); __syncthreads();

    int ksp = warp & 1;          // K split: 0 -> K[0,512), 1 -> K[512,1024)
    int tile = warp >> 1;        // 0..3
    int mi = tile >> 1;          // row half of b
    int nj = tile & 1;           // col tile (W rows nj*16..; nj=1 rows 24-31 are discard-pad)

    for (int t = 0; t < SS; ++t){
        int cur = t & 1, nxt = cur ^ 1;
        const __nv_bfloat16* hhi = g_hhi[cur];
        const __nv_bfloat16* hlo = g_hlo[cur];

        // ---- load full h (hi+lo): 8192 cp16 ----
        #pragma unroll
        for (int i=0;i<32;i++){
            int cid = tid + i*256;           // 0..8191
            int mat = cid >> 12, k2 = cid & 4095;
            int r = k2 >> 7, c16 = k2 & 127; // 32 rows x 128 chunks
            const __nv_bfloat16* src = (mat ? hlo : hhi) + r*HH + c16*8;
            __nv_bfloat16* dst = (mat ? Hl : Hh) + r*WSTE + c16*8;
            cp16(dst, src);
        }
        cp_commit(); cp_wait<0>();
        __syncthreads();

        // ---- sync-free K loop, 2 rotating accumulators ----
        wmma::fragment<wmma::accumulator,16,16,16,float> acc[2];
        wmma::fill_fragment(acc[0], 0.0f);
        wmma::fill_fragment(acc[1], 0.0f);
        {
            const __nv_bfloat16* Ah = Hh + (mi*16)*WSTE + ksp*512;
            const __nv_bfloat16* Al = Hl + (mi*16)*WSTE + ksp*512;
            const __nv_bfloat16* Bh = Wh + (nj*16)*WSTE + ksp*512;
            const __nv_bfloat16* Bl = Wl + (nj*16)*WSTE + ksp*512;
            #pragma unroll 4
            for (int kk = 0; kk < 32; kk++){
                wmma::fragment<wmma::matrix_a,16,16,16,__nv_bfloat16,wmma::row_major> ah, al;
                wmma::fragment<wmma::matrix_b,16,16,16,__nv_bfloat16,wmma::col_major> bh, bl;
                wmma::load_matrix_sync(ah, Ah + kk*16, WSTE);
                wmma::load_matrix_sync(al, Al + kk*16, WSTE);
                wmma::load_matrix_sync(bh, Bh + kk*16, WSTE);
                wmma::load_matrix_sync(bl, Bl + kk*16, WSTE);
                int a = kk & 1;
                wmma::mma_sync(acc[a], ah, bh, acc[a]);
                wmma::mma_sync(acc[a], ah, bl, acc[a]);
                wmma::mma_sync(acc[a], al, bh, acc[a]);
            }
        }
        #pragma unroll
        for (int e = 0; e < acc[0].num_elements; e++) acc[0].x[e] += acc[1].x[e];

        __syncthreads();   // all warps done reading Hh/Hl before CS aliases it
        wmma::store_matrix_sync(CS + warp*256, acc[0], 16, wmma::mem_row_major);
        __syncthreads();

        // ---- gate update: 256 elems (32 b x 8 j), 1 per thread ----
        {
            int b = tid >> 3, jl = tid & 7;
            int j = j0 + jl;
            int bmi = b >> 4, b16 = b & 15;
            int t_rz = bmi*2 + 0, t_n = bmi*2 + 1;
            float ghr = CS[(t_rz*2+0)*256 + b16*16 + jl]     + CS[(t_rz*2+1)*256 + b16*16 + jl];
            float ghz = CS[(t_rz*2+0)*256 + b16*16 + 8 + jl] + CS[(t_rz*2+1)*256 + b16*16 + 8 + jl];
            float ghn = CS[(t_n*2+0)*256  + b16*16 + jl]     + CS[(t_n*2+1)*256  + b16*16 + jl];
            const float* gi = &g_GI[(size_t)(t*BB + b)*H3];
            float gir = gi[j]        + bih[j];
            float giz = gi[HH + j]   + bih[HH + j];
            float gin = gi[2*HH + j] + bih[2*HH + j];
            float r = 1.f/(1.f + expf(-(gir + ghr + bhh[j])));
            float z = 1.f/(1.f + expf(-(giz + ghz + bhh[HH + j])));
            float n = tanhf(gin + r*(ghn + bhh[2*HH + j]));
            float h = (1.f - z)*n + z*g_hf[cur][b*HH + j];
            g_hf[nxt][b*HH + j] = h;
            __nv_bfloat16 hb = __float2bfloat16(h);
            g_hhi[nxt][b*HH + j] = hb;
            g_hlo[nxt][b*HH + j] = __float2bfloat16(h - __bfloat162float(hb));
            g_HSb[(size_t)(t*BB + b)*HH + j] = hb;
        }

        // ---- grid-wide barrier (128 co-resident blocks) ----
        __threadfence();
        __syncthreads();
        if (tid == 0){
            atomicAdd(&g_bar, 1);
            int target = GRU_BLOCKS * (t + 1);
            while (*(volatile int*)&g_bar < target) { }
        }
        __syncthreads();
    }
}

// ---------------- log_softmax in place (online, 2 passes) ----------------
__global__ void lsm_kernel(float* __restrict__ out)
{
    __shared__ float rm[256], rs[256];
    float4* p = (float4*)(out + (size_t)blockIdx.x * VV);
    float m = -1e30f, s = 0.f;
    for (int i = threadIdx.x; i < 8000; i += 256){
        float4 v = p[i];
        float a[4] = {v.x, v.y, v.z, v.w};
        #pragma unroll
        for (int k=0;k<4;k++){
            float x = a[k];
            if (x > m){ s = s * expf(m - x) + 1.f; m = x; }
            else s += expf(x - m);
        }
    }
    rm[threadIdx.x] = m; rs[threadIdx.x] = s; __syncthreads();
    for (int st=128; st>0; st>>=1){
        if (threadIdx.x < st){
            float m2 = rm[threadIdx.x+st], s2 = rs[threadIdx.x+st];
            float m1 = rm[threadIdx.x],    s1 = rs[threadIdx.x];
            float M = fmaxf(m1, m2);
            rm[threadIdx.x] = M;
            rs[threadIdx.x] = s1 * expf(m1 - M) + s2 * expf(m2 - M);
        }
        __syncthreads();
    }
    float lse = rm[0] + logf(rs[0]);
    for (int i = threadIdx.x; i < 8000; i += 256){
        float4 v = p[i];
        v.x -= lse; v.y -= lse; v.z -= lse; v.w -= lse;
        p[i] = v;
    }
}

// ---------------- hT tail ----------------
__global__ void ht_kernel(float* __restrict__ out)
{
    int i = blockIdx.x*blockDim.x + threadIdx.x;
    if (i < BB*HH) out[(size_t)BB*SS*VV + i] = g_hf[0][i];
}

// ---------------- launch ----------------
extern "C" void kernel_launch(void* const* d_in, const int* in_sizes, int n_in,
                              void* d_out, int out_size)
{
    const float* enc_hidden = (const float*)d_in[1];
    const int*   bos        = (const int*)  d_in[2];
    const int*   tgt        = (const int*)  d_in[3];
    const float* emb        = (const float*)d_in[4];
    const float* W_ih       = (const float*)d_in[5];
    const float* W_hh       = (const float*)d_in[6];
    const float* b_ih       = (const float*)d_in[7];
    const float* b_hh       = (const float*)d_in[8];
    const float* W_out      = (const float*)d_in[9];
    const float* b_out      = (const float*)d_in[10];
    float* out = (float*)d_out;

    __nv_bfloat16 *Xb, *Xlo, *Wihb, *Wihlo, *Whhb, *Whhlo, *Woutb, *HSb;
    float *GI;
    cudaGetSymbolAddress((void**)&Xb,    g_Xb);
    cudaGetSymbolAddress((void**)&Xlo,   g_Xlo);
    cudaGetSymbolAddress((void**)&Wihb,  g_Wihb);
    cudaGetSymbolAddress((void**)&Wihlo, g_Wihlo);
    cudaGetSymbolAddress((void**)&Whhb,  g_Whhb);
    cudaGetSymbolAddress((void**)&Whhlo, g_Whhlo);
    cudaGetSymbolAddress((void**)&Woutb, g_Woutb);
    cudaGetSymbolAddress((void**)&HSb,   g_HSb);
    cudaGetSymbolAddress((void**)&GI,    g_GI);

    static int smem_set = 0;
    if (!smem_set){
        cudaFuncSetAttribute(gemm_gi_kernel,     cudaFuncAttributeMaxDynamicSharedMemorySize, 197632);
        cudaFuncSetAttribute(gemm_out_kernel,    cudaFuncAttributeMaxDynamicSharedMemorySize, 197632);
        cudaFuncSetAttribute(gru_persist_kernel, cudaFuncAttributeMaxDynamicSharedMemorySize, GRU_SMEM);
        smem_set = 1;
    }

    {
        size_t n4 = (size_t)H3*HH/4;
        f2b_split_kernel<<<(unsigned)((n4+255)/256), 256>>>(W_ih, Wihb, Wihlo, n4);
        f2b_split_kernel<<<(unsigned)((n4+255)/256), 256>>>(W_hh, Whhb, Whhlo, n4);
    }
    {
        size_t n4 = (size_t)VV*HH/4;
        f2b_kernel<<<(unsigned)((n4+255)/256), 256>>>(W_out, Woutb, n4);
    }

    embed_kernel<<<MM, 256>>>(emb, tgt, bos);
    init_h_kernel<<<BB*HH/256, 256>>>(enc_hidden);

    // GI = X @ W_ih^T (compensated, tcgen05)
    gemm_gi_kernel<<<dim3(H3/256, MM/128), 256, 197632>>>(Xb, Xlo, Wihb, Wihlo, GI);

    // persistent GRU (W + full-h resident, 128 blocks)
    gru_persist_kernel<<<GRU_BLOCKS, 256, GRU_SMEM>>>(b_ih, b_hh);

    // logits = hs @ W_out^T + b_out (tcgen05 256x256, B-sharing grid order)
    gemm_out_kernel<<<dim3(MM/256, VV/256), 512, 197632>>>(HSb, Woutb, out, b_out);

    lsm_kernel<<<MM, 256>>>(out);
    ht_kernel<<<128, 256>>>(out);
}